// round 12
// baseline (speedup 1.0000x reference)
#include <cuda_runtime.h>
#include <cuda_bf16.h>
#include <math.h>
#include <stdint.h>

#define NPATH 100000
#define NLINK 20000
#define TMAX 8
#define NDEG 48
#define DS 64
#define NITERS 4
#define PADK 72   // bf16 H-tile row stride
#define PADX 68   // fp32 X/H-tile row stride (16B-aligned rows)
#define WST 20    // packed-weight row stride in uint2

// Persistent scratch: uninitialized __device__ globals.
__device__ float g_path_state[NPATH * DS];
__device__ float g_link_state[NLINK * DS];
__device__ float g_pss[NPATH * (TMAX + 1) * DS];
__device__ float g_agg[NLINK * 4 * DS];
__device__ float g_t1[NLINK * 128];
__device__ float g_t2[NLINK * 128];
__device__ float g_pa[NLINK * DS];
// Packed GRU weights (path + cell): gate-permuted, bf16 hi/lo, frag-ready uint2.
__device__ uint2 g_wp[4 * 192 * WST];    // path GRU
__device__ uint2 g_wpc[4 * 192 * WST];   // link (cell) GRU
__device__ float g_bih_p[192], g_bhh_p[192];
__device__ float g_bihc_p[192], g_bhhc_p[192];

__device__ __forceinline__ void groupbar(int g) {
    asm volatile("bar.sync %0, 64;" :: "r"(g + 1) : "memory");
}
__device__ __forceinline__ float fsigm(float x) {
    return __fdividef(1.0f, 1.0f + __expf(-x));
}
__device__ __forceinline__ float ftanh(float x) {
    x = fminf(fmaxf(x, -15.0f), 15.0f);
    float e = __expf(-2.0f * x);
    return __fdividef(1.0f - e, 1.0f + e);
}

__device__ __forceinline__ uint32_t packbf(float f0, float f1) {
    __nv_bfloat162 v = __floats2bfloat162_rn(f0, f1);
    return *reinterpret_cast<uint32_t*>(&v);
}
// split float2 -> bf16x2 hi + bf16x2 lo
__device__ __forceinline__ void split2(float2 v, uint32_t& hi, uint32_t& lo) {
    __nv_bfloat162 h = __floats2bfloat162_rn(v.x, v.y);
    hi = *reinterpret_cast<uint32_t*>(&h);
    lo = packbf(v.x - __bfloat162float(h.x), v.y - __bfloat162float(h.y));
}

__device__ __forceinline__ void mma16816(float* c, const uint32_t* a, uint32_t b0, uint32_t b1) {
    asm("mma.sync.aligned.m16n8k16.row.col.f32.bf16.bf16.f32 "
        "{%0,%1,%2,%3}, {%4,%5,%6,%7}, {%8,%9}, {%0,%1,%2,%3};"
        : "+f"(c[0]), "+f"(c[1]), "+f"(c[2]), "+f"(c[3])
        : "r"(a[0]), "r"(a[1]), "r"(a[2]), "r"(a[3]), "r"(b0), "r"(b1));
}

// ---------------------------------------------------------------------------
// Weight prep (path + cell): gate-permute, bf16 hi/lo split, frag-pack.
// ---------------------------------------------------------------------------
__device__ __forceinline__ void pack_w(const float* __restrict__ wih,
                                       const float* __restrict__ whh,
                                       uint2* dst, int i) {
    int r = i >> 4, rem2 = i & 15;
    int kt = rem2 >> 2, tig = rem2 & 3;
    int c = r / 24, rr = r % 24, gate = rr >> 3, u = rr & 7;
    int ro = gate * 64 + c * 8 + u;
    int k0 = kt * 16 + 2 * tig;
    const float* wi = wih + ro * 64;
    const float* wh = whh + ro * 64;
    float fi[4] = { wi[k0], wi[k0 + 1], wi[k0 + 8], wi[k0 + 9] };
    float fh[4] = { wh[k0], wh[k0 + 1], wh[k0 + 8], wh[k0 + 9] };
    float hi_i[4], hi_h[4];
#pragma unroll
    for (int q = 0; q < 4; q++) {
        hi_i[q] = __bfloat162float(__float2bfloat16(fi[q]));
        hi_h[q] = __bfloat162float(__float2bfloat16(fh[q]));
    }
    int o = r * WST + kt * 4 + tig;
    uint2 v;
    v.x = packbf(fi[0], fi[1]);                     v.y = packbf(fi[2], fi[3]);
    dst[0 * 192 * WST + o] = v;
    v.x = packbf(fi[0] - hi_i[0], fi[1] - hi_i[1]); v.y = packbf(fi[2] - hi_i[2], fi[3] - hi_i[3]);
    dst[1 * 192 * WST + o] = v;
    v.x = packbf(fh[0], fh[1]);                     v.y = packbf(fh[2], fh[3]);
    dst[2 * 192 * WST + o] = v;
    v.x = packbf(fh[0] - hi_h[0], fh[1] - hi_h[1]); v.y = packbf(fh[2] - hi_h[2], fh[3] - hi_h[3]);
    dst[3 * 192 * WST + o] = v;
}

__global__ void prep_weights(const float* __restrict__ wih, const float* __restrict__ whh,
                             const float* __restrict__ bih, const float* __restrict__ bhh,
                             const float* __restrict__ cwih, const float* __restrict__ cwhh,
                             const float* __restrict__ cbih, const float* __restrict__ cbhh) {
    int i = blockIdx.x * blockDim.x + threadIdx.x;
    if (i < 192) {
        int c = i / 24, rem = i % 24, gate = rem >> 3, u = rem & 7;
        int ro = gate * 64 + c * 8 + u;
        g_bih_p[i] = bih[ro];   g_bhh_p[i] = bhh[ro];
        g_bihc_p[i] = cbih[ro]; g_bhhc_p[i] = cbhh[ro];
    }
    if (i < 3072) pack_w(wih, whh, g_wp, i);
    else if (i >= 4096 && i < 7168) pack_w(cwih, cwhh, g_wpc, i - 4096);
}

// ---------------------------------------------------------------------------
// cp.async gather of one timestep's x rows into fp32 X tile (zero-fill invalid)
// NTH = threads in block.
// ---------------------------------------------------------------------------
template <int NTH>
__device__ __forceinline__ void gather_async(float* sX, const int* sIdx, int t, int tid) {
    for (int i = tid; i < 128 * 16; i += NTH) {
        int pl = i >> 4, q = i & 15;
        int idx = sIdx[pl * TMAX + t];
        const float* src = g_link_state + (idx >= 0 ? idx : 0) * 64 + q * 4;
        uint32_t dst = (uint32_t)__cvta_generic_to_shared(sX + pl * PADX + q * 4);
        int sz = (idx >= 0) ? 16 : 0;
        asm volatile("cp.async.ca.shared.global [%0], [%1], 16, %2;"
                     :: "r"(dst), "l"(src), "r"(sz) : "memory");
    }
}

// ---------------------------------------------------------------------------
// FUSED path GRU: 256 threads = 8 warps. Warp w owns M=32 rows
// [32*(w&3), +32) = two 16-row MMA tiles, and N-half (w>>2).
// Each B-fragment load feeds both M-tiles (weight crossbar traffic halved).
// ---------------------------------------------------------------------------
__global__ void __launch_bounds__(256, 1) gru_path_mma(const int* __restrict__ l2p) {
    extern __shared__ __align__(16) char smraw[];
    uint2* sW          = (uint2*)smraw;                       // [4][192][WST]
    float* sX          = (float*)(sW + 4 * 192 * WST);        // [128][PADX] fp32
    __nv_bfloat16* sHh = (__nv_bfloat16*)(sX + 128 * PADX);   // [128][PADK]
    __nv_bfloat16* sHl = sHh + 128 * PADK;
    float* sBih        = (float*)(sHl + 128 * PADK);          // [192]
    float* sBhh        = sBih + 192;
    int*   sIdx        = (int*)(sBhh + 192);                  // [128][TMAX]

    int tid = threadIdx.x;
    int pbase = blockIdx.x * 128;

    // stage indices first (gather depends on them)
    for (int i = tid; i < 128 * TMAX; i += 256) {
        int pl = i / TMAX, tt = i % TMAX;
        int p = pbase + pl;
        sIdx[pl * TMAX + tt] = (p < NPATH) ? l2p[p * TMAX + tt] : -1;
    }
    __syncthreads();

    // issue gather(0) while staging everything else
    gather_async<256>(sX, sIdx, 0, tid);
    asm volatile("cp.async.commit_group;" ::: "memory");

    for (int i = tid; i < 4 * 192 * WST; i += 256) sW[i] = g_wp[i];
    if (tid < 192) { sBih[tid] = g_bih_p[tid]; sBhh[tid] = g_bhh_p[tid]; }

    for (int i = tid; i < 128 * 64; i += 256) {
        int pl = i >> 6, k = i & 63;
        int p = pbase + pl;
        float hv = 0.f;
        if (p < NPATH) {
            hv = g_path_state[p * 64 + k];
            g_pss[p * 576 + k] = hv;
        }
        __nv_bfloat16 hh = __float2bfloat16(hv);
        sHh[pl * PADK + k] = hh;
        sHl[pl * PADK + k] = __float2bfloat16(hv - __bfloat162float(hh));
    }
    asm volatile("cp.async.wait_group 0;" ::: "memory");
    __syncthreads();

    int warp = tid >> 5, lane = tid & 31;
    int mw = warp & 3, nh = warp >> 2;
    int gid = lane >> 2, tig = lane & 3;
    // two M-tiles per warp
    int rows0[2], rows1[2];
    rows0[0] = mw * 32 + gid;        rows1[0] = rows0[0] + 8;
    rows0[1] = mw * 32 + 16 + gid;   rows1[1] = rows0[1] + 8;

    for (int t = 0; t < TMAX; t++) {
        // build A fragments for both tiles
        uint32_t aXh[2][4][4], aXl[2][4][4], aHh[2][4][4], aHl[2][4][4];
#pragma unroll
        for (int tl = 0; tl < 2; tl++) {
            int r0 = rows0[tl], r1 = rows1[tl];
#pragma unroll
            for (int kt = 0; kt < 4; kt++) {
                int kb = kt * 16 + 2 * tig;
                float2 v;
                v = *(float2*)(sX + r0 * PADX + kb);     split2(v, aXh[tl][kt][0], aXl[tl][kt][0]);
                v = *(float2*)(sX + r1 * PADX + kb);     split2(v, aXh[tl][kt][1], aXl[tl][kt][1]);
                v = *(float2*)(sX + r0 * PADX + kb + 8); split2(v, aXh[tl][kt][2], aXl[tl][kt][2]);
                v = *(float2*)(sX + r1 * PADX + kb + 8); split2(v, aXh[tl][kt][3], aXl[tl][kt][3]);
                const __nv_bfloat16 *r0p, *r1p;
                r0p = sHh + r0 * PADK + kb; r1p = sHh + r1 * PADK + kb;
                aHh[tl][kt][0] = *(const uint32_t*)(r0p);
                aHh[tl][kt][1] = *(const uint32_t*)(r1p);
                aHh[tl][kt][2] = *(const uint32_t*)(r0p + 8);
                aHh[tl][kt][3] = *(const uint32_t*)(r1p + 8);
                r0p = sHl + r0 * PADK + kb; r1p = sHl + r1 * PADK + kb;
                aHl[tl][kt][0] = *(const uint32_t*)(r0p);
                aHl[tl][kt][1] = *(const uint32_t*)(r1p);
                aHl[tl][kt][2] = *(const uint32_t*)(r0p + 8);
                aHl[tl][kt][3] = *(const uint32_t*)(r1p + 8);
            }
        }
        __syncthreads();   // frag reads done: X free for prefetch, H free for epilogue

        if (t + 1 < TMAX) gather_async<256>(sX, sIdx, t + 1, tid);
        asm volatile("cp.async.commit_group;" ::: "memory");

        for (int c = nh * 4; c < nh * 4 + 4; c++) {
            float ci[2][3][4], ch[2][3][4];
#pragma unroll
            for (int j = 0; j < 3; j++) {
                int nb = c * 24 + j * 8 + 2 * tig;
                float b0 = sBih[nb], b1 = sBih[nb + 1];
                float d0 = sBhh[nb], d1 = sBhh[nb + 1];
#pragma unroll
                for (int tl = 0; tl < 2; tl++) {
                    ci[tl][j][0] = b0; ci[tl][j][1] = b1; ci[tl][j][2] = b0; ci[tl][j][3] = b1;
                    ch[tl][j][0] = d0; ch[tl][j][1] = d1; ch[tl][j][2] = d0; ch[tl][j][3] = d1;
                }
            }
#pragma unroll
            for (int kt = 0; kt < 4; kt++) {
#pragma unroll
                for (int j = 0; j < 3; j++) {
                    int o = (c * 24 + j * 8 + gid) * WST + kt * 4 + tig;
                    uint2 wA = sW[0 * 192 * WST + o];
                    uint2 wB = sW[1 * 192 * WST + o];
                    uint2 wC = sW[2 * 192 * WST + o];
                    uint2 wD = sW[3 * 192 * WST + o];
#pragma unroll
                    for (int tl = 0; tl < 2; tl++) {
                        mma16816(ci[tl][j], aXh[tl][kt], wA.x, wA.y);
                        mma16816(ci[tl][j], aXl[tl][kt], wA.x, wA.y);
                        mma16816(ci[tl][j], aXh[tl][kt], wB.x, wB.y);
                        mma16816(ch[tl][j], aHh[tl][kt], wC.x, wC.y);
                        mma16816(ch[tl][j], aHl[tl][kt], wC.x, wC.y);
                        mma16816(ch[tl][j], aHh[tl][kt], wD.x, wD.y);
                    }
                }
            }
            // epilogue: per-thread GRU update, 2 tiles x 2 rows x 2 units
#pragma unroll
            for (int tl = 0; tl < 2; tl++) {
#pragma unroll
                for (int half = 0; half < 2; half++) {
                    int lrow = (half == 0) ? rows0[tl] : rows1[tl];
                    int p = pbase + lrow;
                    int valid = sIdx[lrow * TMAX + t] >= 0;
                    int ri = half * 2;
                    int ubase = c * 8 + 2 * tig;
                    uint32_t hhp = *(uint32_t*)(sHh + lrow * PADK + ubase);
                    uint32_t hlp = *(uint32_t*)(sHl + lrow * PADK + ubase);
                    __nv_bfloat162 hh2 = *(__nv_bfloat162*)&hhp;
                    __nv_bfloat162 hl2 = *(__nv_bfloat162*)&hlp;
                    float hold0 = __bfloat162float(hh2.x) + __bfloat162float(hl2.x);
                    float hold1 = __bfloat162float(hh2.y) + __bfloat162float(hl2.y);
                    float r0 = fsigm(ci[tl][0][ri] + ch[tl][0][ri]);
                    float z0 = fsigm(ci[tl][1][ri] + ch[tl][1][ri]);
                    float n0 = ftanh(ci[tl][2][ri] + r0 * ch[tl][2][ri]);
                    float hn0 = valid ? ((1.f - z0) * n0 + z0 * hold0) : hold0;
                    float r1 = fsigm(ci[tl][0][ri + 1] + ch[tl][0][ri + 1]);
                    float z1 = fsigm(ci[tl][1][ri + 1] + ch[tl][1][ri + 1]);
                    float n1 = ftanh(ci[tl][2][ri + 1] + r1 * ch[tl][2][ri + 1]);
                    float hn1 = valid ? ((1.f - z1) * n1 + z1 * hold1) : hold1;
                    float h0f = __bfloat162float(__float2bfloat16(hn0));
                    float h1f = __bfloat162float(__float2bfloat16(hn1));
                    *(uint32_t*)(sHh + lrow * PADK + ubase) = packbf(hn0, hn1);
                    *(uint32_t*)(sHl + lrow * PADK + ubase) = packbf(hn0 - h0f, hn1 - h1f);
                    if (p < NPATH) {
                        float2 o2 = make_float2(valid ? hn0 : 0.f, valid ? hn1 : 0.f);
                        *(float2*)(g_pss + p * 576 + (t + 1) * 64 + ubase) = o2;
                    }
                }
            }
        }
        asm volatile("cp.async.wait_group 0;" ::: "memory");
        __syncthreads();   // epilogue h-writes + prefetched X visible
    }

    for (int i = tid; i < 128 * 64; i += 256) {
        int pl = i >> 6, k = i & 63;
        int p = pbase + pl;
        if (p < NPATH)
            g_path_state[p * 64 + k] =
                __bfloat162float(sHh[pl * PADK + k]) + __bfloat162float(sHl[pl * PADK + k]);
    }
}

// ---------------------------------------------------------------------------
// Link GRU via MMA: one step, dense. x = g_pa, h = g_link_state (in/out).
// ---------------------------------------------------------------------------
__global__ void __launch_bounds__(512, 1) gru_link_mma() {
    extern __shared__ __align__(16) char smraw[];
    uint2* sW   = (uint2*)smraw;                      // [4][192][WST]
    float* sX   = (float*)(sW + 4 * 192 * WST);       // [128][PADX]
    float* sH   = sX + 128 * PADX;                    // [128][PADX]
    float* sBih = sH + 128 * PADX;                    // [192]
    float* sBhh = sBih + 192;

    int tid = threadIdx.x;
    int lbase = blockIdx.x * 128;

    for (int i = tid; i < 4 * 192 * WST; i += 512) sW[i] = g_wpc[i];
    if (tid < 192) { sBih[tid] = g_bihc_p[tid]; sBhh[tid] = g_bhhc_p[tid]; }
    for (int i = tid; i < 128 * 64; i += 512) {
        int pl = i >> 6, k = i & 63;
        int l = lbase + pl;
        sX[pl * PADX + k] = (l < NLINK) ? g_pa[l * 64 + k] : 0.f;
        sH[pl * PADX + k] = (l < NLINK) ? g_link_state[l * 64 + k] : 0.f;
    }
    __syncthreads();

    int warp = tid >> 5, lane = tid & 31;
    int mw = warp & 7, nh = warp >> 3;
    int gid = lane >> 2, tig = lane & 3;
    int row0 = mw * 16 + gid;
    int row1 = row0 + 8;

    uint32_t aXh[4][4], aXl[4][4], aHh[4][4], aHl[4][4];
#pragma unroll
    for (int kt = 0; kt < 4; kt++) {
        int kb = kt * 16 + 2 * tig;
        float2 v;
        v = *(float2*)(sX + row0 * PADX + kb);     split2(v, aXh[kt][0], aXl[kt][0]);
        v = *(float2*)(sX + row1 * PADX + kb);     split2(v, aXh[kt][1], aXl[kt][1]);
        v = *(float2*)(sX + row0 * PADX + kb + 8); split2(v, aXh[kt][2], aXl[kt][2]);
        v = *(float2*)(sX + row1 * PADX + kb + 8); split2(v, aXh[kt][3], aXl[kt][3]);
        v = *(float2*)(sH + row0 * PADX + kb);     split2(v, aHh[kt][0], aHl[kt][0]);
        v = *(float2*)(sH + row1 * PADX + kb);     split2(v, aHh[kt][1], aHl[kt][1]);
        v = *(float2*)(sH + row0 * PADX + kb + 8); split2(v, aHh[kt][2], aHl[kt][2]);
        v = *(float2*)(sH + row1 * PADX + kb + 8); split2(v, aHh[kt][3], aHl[kt][3]);
    }

    for (int c = nh * 4; c < nh * 4 + 4; c++) {
        float ci[3][4], ch[3][4];
#pragma unroll
        for (int j = 0; j < 3; j++) {
            int nb = c * 24 + j * 8 + 2 * tig;
            float b0 = sBih[nb], b1 = sBih[nb + 1];
            ci[j][0] = b0; ci[j][1] = b1; ci[j][2] = b0; ci[j][3] = b1;
            float d0 = sBhh[nb], d1 = sBhh[nb + 1];
            ch[j][0] = d0; ch[j][1] = d1; ch[j][2] = d0; ch[j][3] = d1;
        }
#pragma unroll
        for (int kt = 0; kt < 4; kt++) {
#pragma unroll
            for (int j = 0; j < 3; j++) {
                int o = (c * 24 + j * 8 + gid) * WST + kt * 4 + tig;
                uint2 wA = sW[0 * 192 * WST + o];
                uint2 wB = sW[1 * 192 * WST + o];
                uint2 wC = sW[2 * 192 * WST + o];
                uint2 wD = sW[3 * 192 * WST + o];
                mma16816(ci[j], aXh[kt], wA.x, wA.y);
                mma16816(ci[j], aXl[kt], wA.x, wA.y);
                mma16816(ci[j], aXh[kt], wB.x, wB.y);
                mma16816(ch[j], aHh[kt], wC.x, wC.y);
                mma16816(ch[j], aHl[kt], wC.x, wC.y);
                mma16816(ch[j], aHh[kt], wD.x, wD.y);
            }
        }
#pragma unroll
        for (int half = 0; half < 2; half++) {
            int lrow = (half == 0) ? row0 : row1;
            int l = lbase + lrow;
            int ri = half * 2;
            int ubase = c * 8 + 2 * tig;
            float hold0 = sH[lrow * PADX + ubase];
            float hold1 = sH[lrow * PADX + ubase + 1];
            float r0 = fsigm(ci[0][ri] + ch[0][ri]);
            float z0 = fsigm(ci[1][ri] + ch[1][ri]);
            float n0 = ftanh(ci[2][ri] + r0 * ch[2][ri]);
            float hn0 = (1.f - z0) * n0 + z0 * hold0;
            float r1 = fsigm(ci[0][ri + 1] + ch[0][ri + 1]);
            float z1 = fsigm(ci[1][ri + 1] + ch[1][ri + 1]);
            float n1 = ftanh(ci[2][ri + 1] + r1 * ch[2][ri + 1]);
            float hn1 = (1.f - z1) * n1 + z1 * hold1;
            if (l < NLINK)
                *(float2*)(g_link_state + l * 64 + ubase) = make_float2(hn0, hn1);
        }
    }
}

// ---------------------------------------------------------------------------
// Embedding
// ---------------------------------------------------------------------------
template <int TARGET>
__global__ void embed_kernel(const float* __restrict__ x,
                             const float* __restrict__ w1, const float* __restrict__ b1,
                             const float* __restrict__ w2, const float* __restrict__ b2,
                             int n) {
    __shared__ float sWm[64 * 64];
    __shared__ float sw1[64], sb1[64], sb2[64];
    __shared__ float sh1[4][64];
    float* st = (TARGET == 0) ? g_path_state : g_link_state;
    int tid = threadIdx.x;
    for (int i = tid; i < 4096; i += 256) {
        int j = i >> 6, k = i & 63;
        sWm[k * 64 + j] = w2[i];
    }
    if (tid < 64) { sw1[tid] = w1[tid]; sb1[tid] = b1[tid]; sb2[tid] = b2[tid]; }
    __syncthreads();
    int g = tid >> 6, d = tid & 63;
    for (int base = blockIdx.x * 4; base < n; base += gridDim.x * 4) {
        int p = base + g;
        float h1 = 0.0f;
        if (p < n) {
            float t = x[p];
            h1 = fmaxf(t * sw1[d] + sb1[d], 0.0f);
        }
        sh1[g][d] = h1;
        groupbar(g);
        float acc = sb2[d];
#pragma unroll 8
        for (int k = 0; k < 64; k++) acc += sh1[g][k] * sWm[k * 64 + d];
        if (p < n) st[p * 64 + d] = fmaxf(acc, 0.0f);
        groupbar(g);
    }
}

// ---------------------------------------------------------------------------
// Link aggregation (dual accumulator chains for MLP)
// ---------------------------------------------------------------------------
__global__ void agg_kernel(const int* __restrict__ p2l) {
    __shared__ int s_pi[4][NDEG], s_pos[4][NDEG];
    int tid = threadIdx.x;
    int g = tid >> 6, d = tid & 63;
    for (int base = blockIdx.x * 4; base < NLINK; base += gridDim.x * 4) {
        int l = base + g;
        if (l < NLINK && d < NDEG) {
            s_pi[g][d]  = p2l[(l * NDEG + d) * 2];
            s_pos[g][d] = p2l[(l * NDEG + d) * 2 + 1];
        }
        groupbar(g);
        if (l < NLINK) {
            float mn0 = INFINITY, mx0 = -INFINITY, sm0 = 0.0f;
            float mn1 = INFINITY, mx1 = -INFINITY, sm1 = 0.0f;
            int c0 = 0, c1 = 0;
#pragma unroll 4
            for (int e = 0; e < NDEG; e += 2) {
                int pi0 = s_pi[g][e];
                int pi1 = s_pi[g][e + 1];
                if (pi0 >= 0) {
                    float v = g_pss[(pi0 * 9 + s_pos[g][e]) * 64 + d];
                    c0++;
                    mn0 = fminf(mn0, v); mx0 = fmaxf(mx0, v); sm0 += v;
                }
                if (pi1 >= 0) {
                    float v = g_pss[(pi1 * 9 + s_pos[g][e + 1]) * 64 + d];
                    c1++;
                    mn1 = fminf(mn1, v); mx1 = fmaxf(mx1, v); sm1 += v;
                }
            }
            float vmin = fminf(mn0, mn1);
            float vmax = fmaxf(mx0, mx1);
            float vsum = sm0 + sm1;
            int cnt = c0 + c1;
            float mean = vsum / (float)(cnt > 0 ? cnt : 1);
            g_agg[l * 256 + d]        = vmin;
            g_agg[l * 256 + 64 + d]   = vmax;
            g_agg[l * 256 + 128 + d]  = vsum;
            g_agg[l * 256 + 192 + d]  = mean;
        }
        groupbar(g);
    }
}

// ---------------------------------------------------------------------------
// Grouped batched matvec + relu, float4 inner loop.
// SRC/DST: 0=g_agg,1=g_t1,2=g_t2,3=g_pa.
// ---------------------------------------------------------------------------
__device__ __forceinline__ float* buf_sel(int s) {
    if (s == 0) return g_agg;
    if (s == 1) return g_t1;
    if (s == 2) return g_t2;
    return g_pa;
}

template <int IN, int OUT, int NL, int GR, int SRC, int DST>
__global__ void __launch_bounds__(OUT * GR) matvec_relu(const float* __restrict__ W,
                                                        const float* __restrict__ b, int n) {
    extern __shared__ float sm[];
    float* sWT = sm;                 // [IN][OUT] (k-major)
    float* sb  = sWT + IN * OUT;     // OUT
    float* sin = sb + OUT;           // [GR][NL*IN]
    const float* in = buf_sel(SRC);
    float* out = buf_sel(DST);
    int tid = threadIdx.x;
    const int NTH = OUT * GR;
    for (int i = tid; i < IN * OUT; i += NTH) {
        int j = i / IN, k = i % IN;
        sWT[k * OUT + j] = W[i];
    }
    if (tid < OUT) sb[tid] = b[tid];
    __syncthreads();
    int g = tid / OUT, j = tid % OUT;
    float* gin = sin + g * NL * IN;
    for (int l0 = (blockIdx.x * GR + g) * NL; l0 < n; l0 += gridDim.x * GR * NL) {
        // vectorized staging: float4 per thread
        for (int i4 = j; i4 < NL * IN / 4; i4 += OUT) {
            int i = i4 * 4;
            int ll = l0 + i / IN;
            int kk = i % IN;
            float4 v = make_float4(0.f, 0.f, 0.f, 0.f);
            if (ll < n) v = *(const float4*)(in + ll * IN + kk);
            *(float4*)(gin + i) = v;
        }
        asm volatile("bar.sync %0, %1;" :: "r"(g + 1), "r"(OUT) : "memory");
        float acc[NL];
#pragma unroll
        for (int q = 0; q < NL; q++) acc[q] = sb[j];
        for (int k = 0; k < IN; k += 4) {
            float w0 = sWT[k * OUT + j];
            float w1 = sWT[(k + 1) * OUT + j];
            float w2 = sWT[(k + 2) * OUT + j];
            float w3 = sWT[(k + 3) * OUT + j];
#pragma unroll
            for (int q = 0; q < NL; q++) {
                float4 gv = *(const float4*)(gin + q * IN + k);
                acc[q] = fmaf(gv.x, w0, acc[q]);
                acc[q] = fmaf(gv.y, w1, acc[q]);
                acc[q] = fmaf(gv.z, w2, acc[q]);
                acc[q] = fmaf(gv.w, w3, acc[q]);
            }
        }
#pragma unroll
        for (int q = 0; q < NL; q++) {
            int ll = l0 + q;
            if (ll < n) out[ll * OUT + j] = fmaxf(acc[q], 0.0f);
        }
        asm volatile("bar.sync %0, %1;" :: "r"(g + 1), "r"(OUT) : "memory");
    }
}

__global__ void copy_out_kernel(float* __restrict__ out, int out_size) {
    const int n1 = NPATH * DS;
    const int n2 = n1 + NLINK * DS;
    for (int i = blockIdx.x * blockDim.x + threadIdx.x; i < out_size;
         i += gridDim.x * blockDim.x) {
        float v = 0.0f;
        if (i < n1) v = g_path_state[i];
        else if (i < n2) v = g_link_state[i - n1];
        out[i] = v;
    }
}

extern "C" void kernel_launch(void* const* d_in, const int* in_sizes, int n_in,
                              void* d_out, int out_size) {
    const float* traffic   = (const float*)d_in[0];
    const float* capacity  = (const float*)d_in[1];
    const int*   l2p       = (const int*)d_in[2];
    const int*   p2l       = (const int*)d_in[3];
    const float* pe_w1 = (const float*)d_in[4];
    const float* pe_b1 = (const float*)d_in[5];
    const float* pe_w2 = (const float*)d_in[6];
    const float* pe_b2 = (const float*)d_in[7];
    const float* le_w1 = (const float*)d_in[8];
    const float* le_b1 = (const float*)d_in[9];
    const float* le_w2 = (const float*)d_in[10];
    const float* le_b2 = (const float*)d_in[11];
    const float* gru_wih = (const float*)d_in[12];
    const float* gru_whh = (const float*)d_in[13];
    const float* gru_bih = (const float*)d_in[14];
    const float* gru_bhh = (const float*)d_in[15];
    const float* cell_wih = (const float*)d_in[16];
    const float* cell_whh = (const float*)d_in[17];
    const float* cell_bih = (const float*)d_in[18];
    const float* cell_bhh = (const float*)d_in[19];
    const float* am_w1 = (const float*)d_in[20];
    const float* am_b1 = (const float*)d_in[21];
    const float* am_w2 = (const float*)d_in[22];
    const float* am_b2 = (const float*)d_in[23];
    const float* am_w3 = (const float*)d_in[24];
    const float* am_b3 = (const float*)d_in[25];

    const size_t smem_mma  = (size_t)(4 * 192 * WST) * 8 + (size_t)(128 * PADX) * 4
                           + (size_t)(2 * 128 * PADK) * 2 + (size_t)(2 * 192) * 4
                           + (size_t)(128 * TMAX) * 4;
    const size_t smem_link = (size_t)(4 * 192 * WST) * 8 + (size_t)(2 * 128 * PADX) * 4
                           + (size_t)(2 * 192) * 4;
    const size_t smem_l1 = (size_t)(256 * 128 + 128 + 4 * 16 * 256) * 4;   // 197120
    const size_t smem_l2 = (size_t)(128 * 128 + 128 + 4 * 16 * 128) * 4;   // 98816
    const size_t smem_l3 = (size_t)(128 * 64 + 64 + 8 * 16 * 128) * 4;     // 98560

    cudaFuncSetAttribute(gru_path_mma, cudaFuncAttributeMaxDynamicSharedMemorySize, (int)smem_mma);
    cudaFuncSetAttribute(gru_link_mma, cudaFuncAttributeMaxDynamicSharedMemorySize, (int)smem_link);
    cudaFuncSetAttribute(matvec_relu<256, 128, 16, 4, 0, 1>, cudaFuncAttributeMaxDynamicSharedMemorySize, (int)smem_l1);
    cudaFuncSetAttribute(matvec_relu<128, 128, 16, 4, 1, 2>, cudaFuncAttributeMaxDynamicSharedMemorySize, (int)smem_l2);
    cudaFuncSetAttribute(matvec_relu<128, 64, 16, 8, 2, 3>,  cudaFuncAttributeMaxDynamicSharedMemorySize, (int)smem_l3);

    prep_weights<<<28, 256>>>(gru_wih, gru_whh, gru_bih, gru_bhh,
                              cell_wih, cell_whh, cell_bih, cell_bhh);
    embed_kernel<0><<<1024, 256>>>(traffic, pe_w1, pe_b1, pe_w2, pe_b2, NPATH);
    embed_kernel<1><<<512, 256>>>(capacity, le_w1, le_b1, le_w2, le_b2, NLINK);

    const int gru_blocks  = (NPATH + 127) / 128;   // 782
    const int link_blocks = (NLINK + 127) / 128;   // 157

    for (int it = 0; it < NITERS; it++) {
        gru_path_mma<<<gru_blocks, 256, smem_mma>>>(l2p);
        agg_kernel<<<2500, 256>>>(p2l);
        matvec_relu<256, 128, 16, 4, 0, 1><<<313, 512, smem_l1>>>(am_w1, am_b1, NLINK);
        matvec_relu<128, 128, 16, 4, 1, 2><<<313, 512, smem_l2>>>(am_w2, am_b2, NLINK);
        matvec_relu<128, 64, 16, 8, 2, 3><<<157, 512, smem_l3>>>(am_w3, am_b3, NLINK);
        gru_link_mma<<<link_blocks, 512, smem_link>>>();
    }

    copy_out_kernel<<<4096, 256>>>((float*)d_out, out_size);
}

// round 13
// speedup vs baseline: 1.0822x; 1.0822x over previous
#include <cuda_runtime.h>
#include <cuda_bf16.h>
#include <math.h>
#include <stdint.h>

#define NPATH 100000
#define NLINK 20000
#define TMAX 8
#define NDEG 48
#define DS 64
#define NITERS 4
#define PADK 72   // bf16 H-tile row stride
#define PADX 68   // fp32 X/H-tile row stride (16B-aligned rows)
#define WST 20    // packed-weight row stride in uint2

// Persistent scratch: uninitialized __device__ globals.
__device__ float g_path_state[NPATH * DS];
__device__ float g_link_state[NLINK * DS];
__device__ float g_pss[NPATH * (TMAX + 1) * DS];
__device__ float g_agg[NLINK * 4 * DS];
__device__ float g_t1[NLINK * 128];
__device__ float g_t2[NLINK * 128];
__device__ float g_pa[NLINK * DS];
// Packed GRU weights (path + cell): gate-permuted, bf16 hi/lo, frag-ready uint2.
__device__ uint2 g_wp[4 * 192 * WST];    // path GRU
__device__ uint2 g_wpc[4 * 192 * WST];   // link (cell) GRU
__device__ float g_bih_p[192], g_bhh_p[192];
__device__ float g_bihc_p[192], g_bhhc_p[192];

__device__ __forceinline__ void groupbar(int g) {
    asm volatile("bar.sync %0, 64;" :: "r"(g + 1) : "memory");
}
__device__ __forceinline__ float fsigm(float x) {
    return __fdividef(1.0f, 1.0f + __expf(-x));
}
__device__ __forceinline__ float ftanh(float x) {
    x = fminf(fmaxf(x, -15.0f), 15.0f);
    float e = __expf(-2.0f * x);
    return __fdividef(1.0f - e, 1.0f + e);
}

__device__ __forceinline__ uint32_t packbf(float f0, float f1) {
    __nv_bfloat162 v = __floats2bfloat162_rn(f0, f1);
    return *reinterpret_cast<uint32_t*>(&v);
}
// split float2 -> bf16x2 hi + bf16x2 lo
__device__ __forceinline__ void split2(float2 v, uint32_t& hi, uint32_t& lo) {
    __nv_bfloat162 h = __floats2bfloat162_rn(v.x, v.y);
    hi = *reinterpret_cast<uint32_t*>(&h);
    lo = packbf(v.x - __bfloat162float(h.x), v.y - __bfloat162float(h.y));
}

__device__ __forceinline__ void mma16816(float* c, const uint32_t* a, uint32_t b0, uint32_t b1) {
    asm("mma.sync.aligned.m16n8k16.row.col.f32.bf16.bf16.f32 "
        "{%0,%1,%2,%3}, {%4,%5,%6,%7}, {%8,%9}, {%0,%1,%2,%3};"
        : "+f"(c[0]), "+f"(c[1]), "+f"(c[2]), "+f"(c[3])
        : "r"(a[0]), "r"(a[1]), "r"(a[2]), "r"(a[3]), "r"(b0), "r"(b1));
}

// ---------------------------------------------------------------------------
// Weight prep (path + cell): gate-permute, bf16 hi/lo split, frag-pack.
// ---------------------------------------------------------------------------
__device__ __forceinline__ void pack_w(const float* __restrict__ wih,
                                       const float* __restrict__ whh,
                                       uint2* dst, int i) {
    int r = i >> 4, rem2 = i & 15;
    int kt = rem2 >> 2, tig = rem2 & 3;
    int c = r / 24, rr = r % 24, gate = rr >> 3, u = rr & 7;
    int ro = gate * 64 + c * 8 + u;
    int k0 = kt * 16 + 2 * tig;
    const float* wi = wih + ro * 64;
    const float* wh = whh + ro * 64;
    float fi[4] = { wi[k0], wi[k0 + 1], wi[k0 + 8], wi[k0 + 9] };
    float fh[4] = { wh[k0], wh[k0 + 1], wh[k0 + 8], wh[k0 + 9] };
    float hi_i[4], hi_h[4];
#pragma unroll
    for (int q = 0; q < 4; q++) {
        hi_i[q] = __bfloat162float(__float2bfloat16(fi[q]));
        hi_h[q] = __bfloat162float(__float2bfloat16(fh[q]));
    }
    int o = r * WST + kt * 4 + tig;
    uint2 v;
    v.x = packbf(fi[0], fi[1]);                     v.y = packbf(fi[2], fi[3]);
    dst[0 * 192 * WST + o] = v;
    v.x = packbf(fi[0] - hi_i[0], fi[1] - hi_i[1]); v.y = packbf(fi[2] - hi_i[2], fi[3] - hi_i[3]);
    dst[1 * 192 * WST + o] = v;
    v.x = packbf(fh[0], fh[1]);                     v.y = packbf(fh[2], fh[3]);
    dst[2 * 192 * WST + o] = v;
    v.x = packbf(fh[0] - hi_h[0], fh[1] - hi_h[1]); v.y = packbf(fh[2] - hi_h[2], fh[3] - hi_h[3]);
    dst[3 * 192 * WST + o] = v;
}

__global__ void prep_weights(const float* __restrict__ wih, const float* __restrict__ whh,
                             const float* __restrict__ bih, const float* __restrict__ bhh,
                             const float* __restrict__ cwih, const float* __restrict__ cwhh,
                             const float* __restrict__ cbih, const float* __restrict__ cbhh) {
    int i = blockIdx.x * blockDim.x + threadIdx.x;
    if (i < 192) {
        int c = i / 24, rem = i % 24, gate = rem >> 3, u = rem & 7;
        int ro = gate * 64 + c * 8 + u;
        g_bih_p[i] = bih[ro];   g_bhh_p[i] = bhh[ro];
        g_bihc_p[i] = cbih[ro]; g_bhhc_p[i] = cbhh[ro];
    }
    if (i < 3072) pack_w(wih, whh, g_wp, i);
    else if (i >= 4096 && i < 7168) pack_w(cwih, cwhh, g_wpc, i - 4096);
}

// ---------------------------------------------------------------------------
// cp.async gather of one timestep's x rows into fp32 X tile (zero-fill invalid)
// ---------------------------------------------------------------------------
__device__ __forceinline__ void gather_async(float* sX, const int* sIdx, int t, int tid) {
    for (int i = tid; i < 128 * 16; i += 512) {
        int pl = i >> 4, q = i & 15;
        int idx = sIdx[pl * TMAX + t];
        const float* src = g_link_state + (idx >= 0 ? idx : 0) * 64 + q * 4;
        uint32_t dst = (uint32_t)__cvta_generic_to_shared(sX + pl * PADX + q * 4);
        int sz = (idx >= 0) ? 16 : 0;
        asm volatile("cp.async.ca.shared.global [%0], [%1], 16, %2;"
                     :: "r"(dst), "l"(src), "r"(sz) : "memory");
    }
}

// ---------------------------------------------------------------------------
// FUSED path GRU, N-split, cp.async-pipelined. 512 threads = 16 warps.
// Warp w: M-rows [16*(w&7), +16), N-half (w>>3) = chunks [4*nh, +4).
// pss written with streaming hint (write-once; keep link_state hot in L2).
// ---------------------------------------------------------------------------
__global__ void __launch_bounds__(512, 1) gru_path_mma(const int* __restrict__ l2p) {
    extern __shared__ __align__(16) char smraw[];
    uint2* sW          = (uint2*)smraw;                       // [4][192][WST]
    float* sX          = (float*)(sW + 4 * 192 * WST);        // [128][PADX] fp32
    __nv_bfloat16* sHh = (__nv_bfloat16*)(sX + 128 * PADX);   // [128][PADK]
    __nv_bfloat16* sHl = sHh + 128 * PADK;
    float* sBih        = (float*)(sHl + 128 * PADK);          // [192]
    float* sBhh        = sBih + 192;
    int*   sIdx        = (int*)(sBhh + 192);                  // [128][TMAX]

    int tid = threadIdx.x;
    int pbase = blockIdx.x * 128;

    // stage indices first (gather depends on them)
    for (int i = tid; i < 128 * TMAX; i += 512) {
        int pl = i / TMAX, tt = i % TMAX;
        int p = pbase + pl;
        sIdx[pl * TMAX + tt] = (p < NPATH) ? l2p[p * TMAX + tt] : -1;
    }
    __syncthreads();

    // issue gather(0) while staging everything else
    gather_async(sX, sIdx, 0, tid);
    asm volatile("cp.async.commit_group;" ::: "memory");

    for (int i = tid; i < 4 * 192 * WST; i += 512) sW[i] = g_wp[i];
    if (tid < 192) { sBih[tid] = g_bih_p[tid]; sBhh[tid] = g_bhh_p[tid]; }

    for (int i = tid; i < 128 * 64; i += 512) {
        int pl = i >> 6, k = i & 63;
        int p = pbase + pl;
        float hv = 0.f;
        if (p < NPATH) {
            hv = g_path_state[p * 64 + k];
            __stcs(&g_pss[p * 576 + k], hv);
        }
        __nv_bfloat16 hh = __float2bfloat16(hv);
        sHh[pl * PADK + k] = hh;
        sHl[pl * PADK + k] = __float2bfloat16(hv - __bfloat162float(hh));
    }
    asm volatile("cp.async.wait_group 0;" ::: "memory");
    __syncthreads();

    int warp = tid >> 5, lane = tid & 31;
    int mw = warp & 7, nh = warp >> 3;
    int gid = lane >> 2, tig = lane & 3;
    int row0 = mw * 16 + gid;
    int row1 = row0 + 8;

    for (int t = 0; t < TMAX; t++) {
        // build A fragments: X from fp32 tile (split in regs), H from bf16 tiles
        uint32_t aXh[4][4], aXl[4][4], aHh[4][4], aHl[4][4];
#pragma unroll
        for (int kt = 0; kt < 4; kt++) {
            int kb = kt * 16 + 2 * tig;
            float2 v;
            v = *(float2*)(sX + row0 * PADX + kb);     split2(v, aXh[kt][0], aXl[kt][0]);
            v = *(float2*)(sX + row1 * PADX + kb);     split2(v, aXh[kt][1], aXl[kt][1]);
            v = *(float2*)(sX + row0 * PADX + kb + 8); split2(v, aXh[kt][2], aXl[kt][2]);
            v = *(float2*)(sX + row1 * PADX + kb + 8); split2(v, aXh[kt][3], aXl[kt][3]);
            const __nv_bfloat16 *r0p, *r1p;
            r0p = sHh + row0 * PADK + kb; r1p = sHh + row1 * PADK + kb;
            aHh[kt][0] = *(const uint32_t*)(r0p);
            aHh[kt][1] = *(const uint32_t*)(r1p);
            aHh[kt][2] = *(const uint32_t*)(r0p + 8);
            aHh[kt][3] = *(const uint32_t*)(r1p + 8);
            r0p = sHl + row0 * PADK + kb; r1p = sHl + row1 * PADK + kb;
            aHl[kt][0] = *(const uint32_t*)(r0p);
            aHl[kt][1] = *(const uint32_t*)(r1p);
            aHl[kt][2] = *(const uint32_t*)(r0p + 8);
            aHl[kt][3] = *(const uint32_t*)(r1p + 8);
        }
        __syncthreads();   // frag reads done: X tile free for prefetch, H tiles free for epilogue

        if (t + 1 < TMAX) gather_async(sX, sIdx, t + 1, tid);
        asm volatile("cp.async.commit_group;" ::: "memory");

        for (int c = nh * 4; c < nh * 4 + 4; c++) {
            float ci[3][4], ch[3][4];
#pragma unroll
            for (int j = 0; j < 3; j++) {
                int nb = c * 24 + j * 8 + 2 * tig;
                float b0 = sBih[nb], b1 = sBih[nb + 1];
                ci[j][0] = b0; ci[j][1] = b1; ci[j][2] = b0; ci[j][3] = b1;
                float d0 = sBhh[nb], d1 = sBhh[nb + 1];
                ch[j][0] = d0; ch[j][1] = d1; ch[j][2] = d0; ch[j][3] = d1;
            }
#pragma unroll
            for (int kt = 0; kt < 4; kt++) {
#pragma unroll
                for (int j = 0; j < 3; j++) {
                    int o = (c * 24 + j * 8 + gid) * WST + kt * 4 + tig;
                    uint2 wA = sW[0 * 192 * WST + o];
                    uint2 wB = sW[1 * 192 * WST + o];
                    uint2 wC = sW[2 * 192 * WST + o];
                    uint2 wD = sW[3 * 192 * WST + o];
                    mma16816(ci[j], aXh[kt], wA.x, wA.y);
                    mma16816(ci[j], aXl[kt], wA.x, wA.y);
                    mma16816(ci[j], aXh[kt], wB.x, wB.y);
                    mma16816(ch[j], aHh[kt], wC.x, wC.y);
                    mma16816(ch[j], aHl[kt], wC.x, wC.y);
                    mma16816(ch[j], aHh[kt], wD.x, wD.y);
                }
            }
#pragma unroll
            for (int half = 0; half < 2; half++) {
                int lrow = (half == 0) ? row0 : row1;
                int p = pbase + lrow;
                int valid = sIdx[lrow * TMAX + t] >= 0;
                int ri = half * 2;
                int ubase = c * 8 + 2 * tig;
                uint32_t hhp = *(uint32_t*)(sHh + lrow * PADK + ubase);
                uint32_t hlp = *(uint32_t*)(sHl + lrow * PADK + ubase);
                __nv_bfloat162 hh2 = *(__nv_bfloat162*)&hhp;
                __nv_bfloat162 hl2 = *(__nv_bfloat162*)&hlp;
                float hold0 = __bfloat162float(hh2.x) + __bfloat162float(hl2.x);
                float hold1 = __bfloat162float(hh2.y) + __bfloat162float(hl2.y);
                float r0 = fsigm(ci[0][ri] + ch[0][ri]);
                float z0 = fsigm(ci[1][ri] + ch[1][ri]);
                float n0 = ftanh(ci[2][ri] + r0 * ch[2][ri]);
                float hn0 = valid ? ((1.f - z0) * n0 + z0 * hold0) : hold0;
                float r1 = fsigm(ci[0][ri + 1] + ch[0][ri + 1]);
                float z1 = fsigm(ci[1][ri + 1] + ch[1][ri + 1]);
                float n1 = ftanh(ci[2][ri + 1] + r1 * ch[2][ri + 1]);
                float hn1 = valid ? ((1.f - z1) * n1 + z1 * hold1) : hold1;
                float h0f = __bfloat162float(__float2bfloat16(hn0));
                float h1f = __bfloat162float(__float2bfloat16(hn1));
                *(uint32_t*)(sHh + lrow * PADK + ubase) = packbf(hn0, hn1);
                *(uint32_t*)(sHl + lrow * PADK + ubase) = packbf(hn0 - h0f, hn1 - h1f);
                if (p < NPATH) {
                    float2 o2 = make_float2(valid ? hn0 : 0.f, valid ? hn1 : 0.f);
                    __stcs((float2*)(g_pss + p * 576 + (t + 1) * 64 + ubase), o2);
                }
            }
        }
        asm volatile("cp.async.wait_group 0;" ::: "memory");
        __syncthreads();   // epilogue h-writes + prefetched X visible
    }

    for (int i = tid; i < 128 * 64; i += 512) {
        int pl = i >> 6, k = i & 63;
        int p = pbase + pl;
        if (p < NPATH)
            g_path_state[p * 64 + k] =
                __bfloat162float(sHh[pl * PADK + k]) + __bfloat162float(sHl[pl * PADK + k]);
    }
}

// ---------------------------------------------------------------------------
// Link GRU via MMA: one step, dense. x = g_pa, h = g_link_state (in/out).
// ---------------------------------------------------------------------------
__global__ void __launch_bounds__(512, 1) gru_link_mma() {
    extern __shared__ __align__(16) char smraw[];
    uint2* sW   = (uint2*)smraw;                      // [4][192][WST]
    float* sX   = (float*)(sW + 4 * 192 * WST);       // [128][PADX]
    float* sH   = sX + 128 * PADX;                    // [128][PADX]
    float* sBih = sH + 128 * PADX;                    // [192]
    float* sBhh = sBih + 192;

    int tid = threadIdx.x;
    int lbase = blockIdx.x * 128;

    for (int i = tid; i < 4 * 192 * WST; i += 512) sW[i] = g_wpc[i];
    if (tid < 192) { sBih[tid] = g_bihc_p[tid]; sBhh[tid] = g_bhhc_p[tid]; }
    for (int i = tid; i < 128 * 64; i += 512) {
        int pl = i >> 6, k = i & 63;
        int l = lbase + pl;
        sX[pl * PADX + k] = (l < NLINK) ? g_pa[l * 64 + k] : 0.f;
        sH[pl * PADX + k] = (l < NLINK) ? g_link_state[l * 64 + k] : 0.f;
    }
    __syncthreads();

    int warp = tid >> 5, lane = tid & 31;
    int mw = warp & 7, nh = warp >> 3;
    int gid = lane >> 2, tig = lane & 3;
    int row0 = mw * 16 + gid;
    int row1 = row0 + 8;

    uint32_t aXh[4][4], aXl[4][4], aHh[4][4], aHl[4][4];
#pragma unroll
    for (int kt = 0; kt < 4; kt++) {
        int kb = kt * 16 + 2 * tig;
        float2 v;
        v = *(float2*)(sX + row0 * PADX + kb);     split2(v, aXh[kt][0], aXl[kt][0]);
        v = *(float2*)(sX + row1 * PADX + kb);     split2(v, aXh[kt][1], aXl[kt][1]);
        v = *(float2*)(sX + row0 * PADX + kb + 8); split2(v, aXh[kt][2], aXl[kt][2]);
        v = *(float2*)(sX + row1 * PADX + kb + 8); split2(v, aXh[kt][3], aXl[kt][3]);
        v = *(float2*)(sH + row0 * PADX + kb);     split2(v, aHh[kt][0], aHl[kt][0]);
        v = *(float2*)(sH + row1 * PADX + kb);     split2(v, aHh[kt][1], aHl[kt][1]);
        v = *(float2*)(sH + row0 * PADX + kb + 8); split2(v, aHh[kt][2], aHl[kt][2]);
        v = *(float2*)(sH + row1 * PADX + kb + 8); split2(v, aHh[kt][3], aHl[kt][3]);
    }

    for (int c = nh * 4; c < nh * 4 + 4; c++) {
        float ci[3][4], ch[3][4];
#pragma unroll
        for (int j = 0; j < 3; j++) {
            int nb = c * 24 + j * 8 + 2 * tig;
            float b0 = sBih[nb], b1 = sBih[nb + 1];
            ci[j][0] = b0; ci[j][1] = b1; ci[j][2] = b0; ci[j][3] = b1;
            float d0 = sBhh[nb], d1 = sBhh[nb + 1];
            ch[j][0] = d0; ch[j][1] = d1; ch[j][2] = d0; ch[j][3] = d1;
        }
#pragma unroll
        for (int kt = 0; kt < 4; kt++) {
#pragma unroll
            for (int j = 0; j < 3; j++) {
                int o = (c * 24 + j * 8 + gid) * WST + kt * 4 + tig;
                uint2 wA = sW[0 * 192 * WST + o];
                uint2 wB = sW[1 * 192 * WST + o];
                uint2 wC = sW[2 * 192 * WST + o];
                uint2 wD = sW[3 * 192 * WST + o];
                mma16816(ci[j], aXh[kt], wA.x, wA.y);
                mma16816(ci[j], aXl[kt], wA.x, wA.y);
                mma16816(ci[j], aXh[kt], wB.x, wB.y);
                mma16816(ch[j], aHh[kt], wC.x, wC.y);
                mma16816(ch[j], aHl[kt], wC.x, wC.y);
                mma16816(ch[j], aHh[kt], wD.x, wD.y);
            }
        }
#pragma unroll
        for (int half = 0; half < 2; half++) {
            int lrow = (half == 0) ? row0 : row1;
            int l = lbase + lrow;
            int ri = half * 2;
            int ubase = c * 8 + 2 * tig;
            float hold0 = sH[lrow * PADX + ubase];
            float hold1 = sH[lrow * PADX + ubase + 1];
            float r0 = fsigm(ci[0][ri] + ch[0][ri]);
            float z0 = fsigm(ci[1][ri] + ch[1][ri]);
            float n0 = ftanh(ci[2][ri] + r0 * ch[2][ri]);
            float hn0 = (1.f - z0) * n0 + z0 * hold0;
            float r1 = fsigm(ci[0][ri + 1] + ch[0][ri + 1]);
            float z1 = fsigm(ci[1][ri + 1] + ch[1][ri + 1]);
            float n1 = ftanh(ci[2][ri + 1] + r1 * ch[2][ri + 1]);
            float hn1 = (1.f - z1) * n1 + z1 * hold1;
            if (l < NLINK)
                *(float2*)(g_link_state + l * 64 + ubase) = make_float2(hn0, hn1);
        }
    }
}

// ---------------------------------------------------------------------------
// Embedding
// ---------------------------------------------------------------------------
template <int TARGET>
__global__ void embed_kernel(const float* __restrict__ x,
                             const float* __restrict__ w1, const float* __restrict__ b1,
                             const float* __restrict__ w2, const float* __restrict__ b2,
                             int n) {
    __shared__ float sWm[64 * 64];
    __shared__ float sw1[64], sb1[64], sb2[64];
    __shared__ float sh1[4][64];
    float* st = (TARGET == 0) ? g_path_state : g_link_state;
    int tid = threadIdx.x;
    for (int i = tid; i < 4096; i += 256) {
        int j = i >> 6, k = i & 63;
        sWm[k * 64 + j] = w2[i];
    }
    if (tid < 64) { sw1[tid] = w1[tid]; sb1[tid] = b1[tid]; sb2[tid] = b2[tid]; }
    __syncthreads();
    int g = tid >> 6, d = tid & 63;
    for (int base = blockIdx.x * 4; base < n; base += gridDim.x * 4) {
        int p = base + g;
        float h1 = 0.0f;
        if (p < n) {
            float t = x[p];
            h1 = fmaxf(t * sw1[d] + sb1[d], 0.0f);
        }
        sh1[g][d] = h1;
        groupbar(g);
        float acc = sb2[d];
#pragma unroll 8
        for (int k = 0; k < 64; k++) acc += sh1[g][k] * sWm[k * 64 + d];
        if (p < n) st[p * 64 + d] = fmaxf(acc, 0.0f);
        groupbar(g);
    }
}

// ---------------------------------------------------------------------------
// Link aggregation (dual accumulator chains for MLP)
// ---------------------------------------------------------------------------
__global__ void agg_kernel(const int* __restrict__ p2l) {
    __shared__ int s_pi[4][NDEG], s_pos[4][NDEG];
    int tid = threadIdx.x;
    int g = tid >> 6, d = tid & 63;
    for (int base = blockIdx.x * 4; base < NLINK; base += gridDim.x * 4) {
        int l = base + g;
        if (l < NLINK && d < NDEG) {
            s_pi[g][d]  = p2l[(l * NDEG + d) * 2];
            s_pos[g][d] = p2l[(l * NDEG + d) * 2 + 1];
        }
        groupbar(g);
        if (l < NLINK) {
            float mn0 = INFINITY, mx0 = -INFINITY, sm0 = 0.0f;
            float mn1 = INFINITY, mx1 = -INFINITY, sm1 = 0.0f;
            int c0 = 0, c1 = 0;
#pragma unroll 4
            for (int e = 0; e < NDEG; e += 2) {
                int pi0 = s_pi[g][e];
                int pi1 = s_pi[g][e + 1];
                if (pi0 >= 0) {
                    float v = g_pss[(pi0 * 9 + s_pos[g][e]) * 64 + d];
                    c0++;
                    mn0 = fminf(mn0, v); mx0 = fmaxf(mx0, v); sm0 += v;
                }
                if (pi1 >= 0) {
                    float v = g_pss[(pi1 * 9 + s_pos[g][e + 1]) * 64 + d];
                    c1++;
                    mn1 = fminf(mn1, v); mx1 = fmaxf(mx1, v); sm1 += v;
                }
            }
            float vmin = fminf(mn0, mn1);
            float vmax = fmaxf(mx0, mx1);
            float vsum = sm0 + sm1;
            int cnt = c0 + c1;
            float mean = vsum / (float)(cnt > 0 ? cnt : 1);
            g_agg[l * 256 + d]        = vmin;
            g_agg[l * 256 + 64 + d]   = vmax;
            g_agg[l * 256 + 128 + d]  = vsum;
            g_agg[l * 256 + 192 + d]  = mean;
        }
        groupbar(g);
    }
}

// ---------------------------------------------------------------------------
// Grouped batched matvec + relu, float4 inner loop.
// SRC/DST: 0=g_agg,1=g_t1,2=g_t2,3=g_pa.
// ---------------------------------------------------------------------------
__device__ __forceinline__ float* buf_sel(int s) {
    if (s == 0) return g_agg;
    if (s == 1) return g_t1;
    if (s == 2) return g_t2;
    return g_pa;
}

template <int IN, int OUT, int NL, int GR, int SRC, int DST>
__global__ void __launch_bounds__(OUT * GR) matvec_relu(const float* __restrict__ W,
                                                        const float* __restrict__ b, int n) {
    extern __shared__ float sm[];
    float* sWT = sm;                 // [IN][OUT] (k-major)
    float* sb  = sWT + IN * OUT;     // OUT
    float* sin = sb + OUT;           // [GR][NL*IN]
    const float* in = buf_sel(SRC);
    float* out = buf_sel(DST);
    int tid = threadIdx.x;
    const int NTH = OUT * GR;
    for (int i = tid; i < IN * OUT; i += NTH) {
        int j = i / IN, k = i % IN;
        sWT[k * OUT + j] = W[i];
    }
    if (tid < OUT) sb[tid] = b[tid];
    __syncthreads();
    int g = tid / OUT, j = tid % OUT;
    float* gin = sin + g * NL * IN;
    for (int l0 = (blockIdx.x * GR + g) * NL; l0 < n; l0 += gridDim.x * GR * NL) {
        // vectorized staging: float4 per thread
        for (int i4 = j; i4 < NL * IN / 4; i4 += OUT) {
            int i = i4 * 4;
            int ll = l0 + i / IN;
            int kk = i % IN;
            float4 v = make_float4(0.f, 0.f, 0.f, 0.f);
            if (ll < n) v = *(const float4*)(in + ll * IN + kk);
            *(float4*)(gin + i) = v;
        }
        asm volatile("bar.sync %0, %1;" :: "r"(g + 1), "r"(OUT) : "memory");
        float acc[NL];
#pragma unroll
        for (int q = 0; q < NL; q++) acc[q] = sb[j];
        for (int k = 0; k < IN; k += 4) {
            float w0 = sWT[k * OUT + j];
            float w1 = sWT[(k + 1) * OUT + j];
            float w2 = sWT[(k + 2) * OUT + j];
            float w3 = sWT[(k + 3) * OUT + j];
#pragma unroll
            for (int q = 0; q < NL; q++) {
                float4 gv = *(const float4*)(gin + q * IN + k);
                acc[q] = fmaf(gv.x, w0, acc[q]);
                acc[q] = fmaf(gv.y, w1, acc[q]);
                acc[q] = fmaf(gv.z, w2, acc[q]);
                acc[q] = fmaf(gv.w, w3, acc[q]);
            }
        }
#pragma unroll
        for (int q = 0; q < NL; q++) {
            int ll = l0 + q;
            if (ll < n) out[ll * OUT + j] = fmaxf(acc[q], 0.0f);
        }
        asm volatile("bar.sync %0, %1;" :: "r"(g + 1), "r"(OUT) : "memory");
    }
}

__global__ void copy_out_kernel(float* __restrict__ out, int out_size) {
    const int n1 = NPATH * DS;
    const int n2 = n1 + NLINK * DS;
    for (int i = blockIdx.x * blockDim.x + threadIdx.x; i < out_size;
         i += gridDim.x * blockDim.x) {
        float v = 0.0f;
        if (i < n1) v = g_path_state[i];
        else if (i < n2) v = g_link_state[i - n1];
        out[i] = v;
    }
}

extern "C" void kernel_launch(void* const* d_in, const int* in_sizes, int n_in,
                              void* d_out, int out_size) {
    const float* traffic   = (const float*)d_in[0];
    const float* capacity  = (const float*)d_in[1];
    const int*   l2p       = (const int*)d_in[2];
    const int*   p2l       = (const int*)d_in[3];
    const float* pe_w1 = (const float*)d_in[4];
    const float* pe_b1 = (const float*)d_in[5];
    const float* pe_w2 = (const float*)d_in[6];
    const float* pe_b2 = (const float*)d_in[7];
    const float* le_w1 = (const float*)d_in[8];
    const float* le_b1 = (const float*)d_in[9];
    const float* le_w2 = (const float*)d_in[10];
    const float* le_b2 = (const float*)d_in[11];
    const float* gru_wih = (const float*)d_in[12];
    const float* gru_whh = (const float*)d_in[13];
    const float* gru_bih = (const float*)d_in[14];
    const float* gru_bhh = (const float*)d_in[15];
    const float* cell_wih = (const float*)d_in[16];
    const float* cell_whh = (const float*)d_in[17];
    const float* cell_bih = (const float*)d_in[18];
    const float* cell_bhh = (const float*)d_in[19];
    const float* am_w1 = (const float*)d_in[20];
    const float* am_b1 = (const float*)d_in[21];
    const float* am_w2 = (const float*)d_in[22];
    const float* am_b2 = (const float*)d_in[23];
    const float* am_w3 = (const float*)d_in[24];
    const float* am_b3 = (const float*)d_in[25];

    const size_t smem_mma  = (size_t)(4 * 192 * WST) * 8 + (size_t)(128 * PADX) * 4
                           + (size_t)(2 * 128 * PADK) * 2 + (size_t)(2 * 192) * 4
                           + (size_t)(128 * TMAX) * 4;
    const size_t smem_link = (size_t)(4 * 192 * WST) * 8 + (size_t)(2 * 128 * PADX) * 4
                           + (size_t)(2 * 192) * 4;
    const size_t smem_l1 = (size_t)(256 * 128 + 128 + 4 * 16 * 256) * 4;
    const size_t smem_l2 = (size_t)(128 * 128 + 128 + 4 * 16 * 128) * 4;
    const size_t smem_l3 = (size_t)(128 * 64 + 64 + 8 * 16 * 128) * 4;

    cudaFuncSetAttribute(gru_path_mma, cudaFuncAttributeMaxDynamicSharedMemorySize, (int)smem_mma);
    cudaFuncSetAttribute(gru_link_mma, cudaFuncAttributeMaxDynamicSharedMemorySize, (int)smem_link);
    cudaFuncSetAttribute(matvec_relu<256, 128, 16, 4, 0, 1>, cudaFuncAttributeMaxDynamicSharedMemorySize, (int)smem_l1);
    cudaFuncSetAttribute(matvec_relu<128, 128, 16, 4, 1, 2>, cudaFuncAttributeMaxDynamicSharedMemorySize, (int)smem_l2);
    cudaFuncSetAttribute(matvec_relu<128, 64, 16, 8, 2, 3>,  cudaFuncAttributeMaxDynamicSharedMemorySize, (int)smem_l3);

    prep_weights<<<28, 256>>>(gru_wih, gru_whh, gru_bih, gru_bhh,
                              cell_wih, cell_whh, cell_bih, cell_bhh);
    embed_kernel<0><<<3125, 256>>>(traffic, pe_w1, pe_b1, pe_w2, pe_b2, NPATH);
    embed_kernel<1><<<625, 256>>>(capacity, le_w1, le_b1, le_w2, le_b2, NLINK);

    const int gru_blocks  = (NPATH + 127) / 128;   // 782
    const int link_blocks = (NLINK + 127) / 128;   // 157

    for (int it = 0; it < NITERS; it++) {
        gru_path_mma<<<gru_blocks, 512, smem_mma>>>(l2p);
        agg_kernel<<<2500, 256>>>(p2l);
        matvec_relu<256, 128, 16, 4, 0, 1><<<313, 512, smem_l1>>>(am_w1, am_b1, NLINK);
        matvec_relu<128, 128, 16, 4, 1, 2><<<313, 512, smem_l2>>>(am_w2, am_b2, NLINK);
        matvec_relu<128, 64, 16, 8, 2, 3><<<157, 512, smem_l3>>>(am_w3, am_b3, NLINK);
        gru_link_mma<<<link_blocks, 512, smem_link>>>();
    }

    copy_out_kernel<<<4096, 256>>>((float*)d_out, out_size);
}

// round 14
// speedup vs baseline: 1.2433x; 1.1489x over previous
#include <cuda_runtime.h>
#include <cuda_bf16.h>
#include <math.h>
#include <stdint.h>

#define NPATH 100000
#define NLINK 20000
#define TMAX 8
#define NDEG 48
#define DS 64
#define NITERS 4
#define PADK 72   // bf16 H-tile row stride
#define PADX 68   // fp32 X/H-tile row stride (16B-aligned rows)
#define WST 20    // packed-weight row stride in uint2

// Persistent scratch: uninitialized __device__ globals.
__device__ float g_path_state[NPATH * DS];
__device__ float g_link_state[NLINK * DS];
__device__ float g_pss[NPATH * (TMAX + 1) * DS];
__device__ float g_agg[NLINK * 4 * DS];
__device__ float g_t1[NLINK * 128];
__device__ float g_t2[NLINK * 128];
__device__ float g_pa[NLINK * DS];
// Packed GRU weights (path + cell): gate-permuted, bf16 hi/lo, frag-ready uint2.
__device__ uint2 g_wp[4 * 192 * WST];    // path GRU
__device__ uint2 g_wpc[4 * 192 * WST];   // link (cell) GRU
__device__ float g_bih_p[192], g_bhh_p[192];
__device__ float g_bihc_p[192], g_bhhc_p[192];
// Length-sorted path order (counting sort by path length).
__device__ int g_len[NPATH];
__device__ int g_order[NPATH];
__device__ int g_hist[16];
__device__ int g_boff[16];

__device__ __forceinline__ void groupbar(int g) {
    asm volatile("bar.sync %0, 64;" :: "r"(g + 1) : "memory");
}
__device__ __forceinline__ float fsigm(float x) {
    return __fdividef(1.0f, 1.0f + __expf(-x));
}
__device__ __forceinline__ float ftanh(float x) {
    x = fminf(fmaxf(x, -15.0f), 15.0f);
    float e = __expf(-2.0f * x);
    return __fdividef(1.0f - e, 1.0f + e);
}

__device__ __forceinline__ uint32_t packbf(float f0, float f1) {
    __nv_bfloat162 v = __floats2bfloat162_rn(f0, f1);
    return *reinterpret_cast<uint32_t*>(&v);
}
// split float2 -> bf16x2 hi + bf16x2 lo
__device__ __forceinline__ void split2(float2 v, uint32_t& hi, uint32_t& lo) {
    __nv_bfloat162 h = __floats2bfloat162_rn(v.x, v.y);
    hi = *reinterpret_cast<uint32_t*>(&h);
    lo = packbf(v.x - __bfloat162float(h.x), v.y - __bfloat162float(h.y));
}

__device__ __forceinline__ void mma16816(float* c, const uint32_t* a, uint32_t b0, uint32_t b1) {
    asm("mma.sync.aligned.m16n8k16.row.col.f32.bf16.bf16.f32 "
        "{%0,%1,%2,%3}, {%4,%5,%6,%7}, {%8,%9}, {%0,%1,%2,%3};"
        : "+f"(c[0]), "+f"(c[1]), "+f"(c[2]), "+f"(c[3])
        : "r"(a[0]), "r"(a[1]), "r"(a[2]), "r"(a[3]), "r"(b0), "r"(b1));
}

// ---------------------------------------------------------------------------
// Length sort: histogram -> bucket offsets -> scatter. Output order groups
// paths by length ascending; within-bucket order is arbitrary (results are
// order-invariant: all GRU work is indexed by true path id).
// ---------------------------------------------------------------------------
__global__ void zero_hist_kernel() {
    if (threadIdx.x < 16) { g_hist[threadIdx.x] = 0; g_boff[threadIdx.x] = 0; }
}
__global__ void len_hist_kernel(const int* __restrict__ l2p) {
    int p = blockIdx.x * blockDim.x + threadIdx.x;
    if (p < NPATH) {
        int len = 0;
#pragma unroll
        for (int t = 0; t < TMAX; t++) len += (l2p[p * TMAX + t] != -1) ? 1 : 0;
        g_len[p] = len;
        atomicAdd(&g_hist[len], 1);
    }
}
__global__ void bucket_offsets_kernel() {
    if (threadIdx.x == 0) {
        int acc = 0;
        for (int i = 0; i <= TMAX; i++) { g_boff[i] = acc; acc += g_hist[i]; }
    }
}
__global__ void scatter_order_kernel() {
    int p = blockIdx.x * blockDim.x + threadIdx.x;
    if (p < NPATH) {
        int pos = atomicAdd(&g_boff[g_len[p]], 1);
        g_order[pos] = p;
    }
}

// ---------------------------------------------------------------------------
// Weight prep (path + cell): gate-permute, bf16 hi/lo split, frag-pack.
// ---------------------------------------------------------------------------
__device__ __forceinline__ void pack_w(const float* __restrict__ wih,
                                       const float* __restrict__ whh,
                                       uint2* dst, int i) {
    int r = i >> 4, rem2 = i & 15;
    int kt = rem2 >> 2, tig = rem2 & 3;
    int c = r / 24, rr = r % 24, gate = rr >> 3, u = rr & 7;
    int ro = gate * 64 + c * 8 + u;
    int k0 = kt * 16 + 2 * tig;
    const float* wi = wih + ro * 64;
    const float* wh = whh + ro * 64;
    float fi[4] = { wi[k0], wi[k0 + 1], wi[k0 + 8], wi[k0 + 9] };
    float fh[4] = { wh[k0], wh[k0 + 1], wh[k0 + 8], wh[k0 + 9] };
    float hi_i[4], hi_h[4];
#pragma unroll
    for (int q = 0; q < 4; q++) {
        hi_i[q] = __bfloat162float(__float2bfloat16(fi[q]));
        hi_h[q] = __bfloat162float(__float2bfloat16(fh[q]));
    }
    int o = r * WST + kt * 4 + tig;
    uint2 v;
    v.x = packbf(fi[0], fi[1]);                     v.y = packbf(fi[2], fi[3]);
    dst[0 * 192 * WST + o] = v;
    v.x = packbf(fi[0] - hi_i[0], fi[1] - hi_i[1]); v.y = packbf(fi[2] - hi_i[2], fi[3] - hi_i[3]);
    dst[1 * 192 * WST + o] = v;
    v.x = packbf(fh[0], fh[1]);                     v.y = packbf(fh[2], fh[3]);
    dst[2 * 192 * WST + o] = v;
    v.x = packbf(fh[0] - hi_h[0], fh[1] - hi_h[1]); v.y = packbf(fh[2] - hi_h[2], fh[3] - hi_h[3]);
    dst[3 * 192 * WST + o] = v;
}

__global__ void prep_weights(const float* __restrict__ wih, const float* __restrict__ whh,
                             const float* __restrict__ bih, const float* __restrict__ bhh,
                             const float* __restrict__ cwih, const float* __restrict__ cwhh,
                             const float* __restrict__ cbih, const float* __restrict__ cbhh) {
    int i = blockIdx.x * blockDim.x + threadIdx.x;
    if (i < 192) {
        int c = i / 24, rem = i % 24, gate = rem >> 3, u = rem & 7;
        int ro = gate * 64 + c * 8 + u;
        g_bih_p[i] = bih[ro];   g_bhh_p[i] = bhh[ro];
        g_bihc_p[i] = cbih[ro]; g_bhhc_p[i] = cbhh[ro];
    }
    if (i < 3072) pack_w(wih, whh, g_wp, i);
    else if (i >= 4096 && i < 7168) pack_w(cwih, cwhh, g_wpc, i - 4096);
}

// ---------------------------------------------------------------------------
// cp.async gather of one timestep's x rows into fp32 X tile (zero-fill invalid)
// ---------------------------------------------------------------------------
__device__ __forceinline__ void gather_async(float* sX, const int* sIdx, int t, int tid) {
    for (int i = tid; i < 128 * 16; i += 512) {
        int pl = i >> 4, q = i & 15;
        int idx = sIdx[pl * TMAX + t];
        const float* src = g_link_state + (idx >= 0 ? idx : 0) * 64 + q * 4;
        uint32_t dst = (uint32_t)__cvta_generic_to_shared(sX + pl * PADX + q * 4);
        int sz = (idx >= 0) ? 16 : 0;
        asm volatile("cp.async.ca.shared.global [%0], [%1], 16, %2;"
                     :: "r"(dst), "l"(src), "r"(sz) : "memory");
    }
}

// ---------------------------------------------------------------------------
// FUSED path GRU over LENGTH-SORTED paths. 512 threads = 16 warps.
// Block's main loop runs only blockmax-length steps; pss tail zeros are
// pre-written in staging. Warp w: M-rows [16*(w&7), +16), N-half (w>>3).
// ---------------------------------------------------------------------------
__global__ void __launch_bounds__(512, 1) gru_path_mma(const int* __restrict__ l2p) {
    extern __shared__ __align__(16) char smraw[];
    uint2* sW          = (uint2*)smraw;                       // [4][192][WST]
    float* sX          = (float*)(sW + 4 * 192 * WST);        // [128][PADX] fp32
    __nv_bfloat16* sHh = (__nv_bfloat16*)(sX + 128 * PADX);   // [128][PADK]
    __nv_bfloat16* sHl = sHh + 128 * PADK;
    float* sBih        = (float*)(sHl + 128 * PADK);          // [192]
    float* sBhh        = sBih + 192;
    int*   sIdx        = (int*)(sBhh + 192);                  // [128][TMAX]
    int*   sOrd        = sIdx + 128 * TMAX;                   // [128]
    int*   sLen        = sOrd + 128;                          // [128]
    int*   sBmax       = sLen + 128;                          // [1]

    int tid = threadIdx.x;
    int pbase = blockIdx.x * 128;

    if (tid < 128) {
        int gp = pbase + tid;
        sOrd[tid] = (gp < NPATH) ? g_order[gp] : -1;
    }
    if (tid == 0) *sBmax = 0;
    __syncthreads();

    // stage indices + lengths
    for (int i = tid; i < 128 * TMAX; i += 512) {
        int pl = i / TMAX, tt = i % TMAX;
        int p = sOrd[pl];
        sIdx[pl * TMAX + tt] = (p >= 0) ? l2p[p * TMAX + tt] : -1;
    }
    if (tid < 128) {
        int p = sOrd[tid];
        int L = (p >= 0) ? g_len[p] : 0;
        sLen[tid] = L;
        atomicMax(sBmax, L);
    }
    __syncthreads();

    // issue gather(0) while staging everything else
    gather_async(sX, sIdx, 0, tid);
    asm volatile("cp.async.commit_group;" ::: "memory");

    for (int i = tid; i < 4 * 192 * WST; i += 512) sW[i] = g_wp[i];
    if (tid < 192) { sBih[tid] = g_bih_p[tid]; sBhh[tid] = g_bhh_p[tid]; }

    for (int i = tid; i < 128 * 64; i += 512) {
        int pl = i >> 6, k = i & 63;
        int p = sOrd[pl];
        float hv = 0.f;
        if (p >= 0) {
            hv = g_path_state[p * 64 + k];
            __stcs(&g_pss[p * 576 + k], hv);
            // tail zeros: pss[t+1] = 0 for t in [len, TMAX)
            for (int tt = sLen[pl]; tt < TMAX; tt++)
                __stcs(&g_pss[p * 576 + (tt + 1) * 64 + k], 0.f);
        }
        __nv_bfloat16 hh = __float2bfloat16(hv);
        sHh[pl * PADK + k] = hh;
        sHl[pl * PADK + k] = __float2bfloat16(hv - __bfloat162float(hh));
    }
    asm volatile("cp.async.wait_group 0;" ::: "memory");
    __syncthreads();

    int blockLen = *sBmax;
    int warp = tid >> 5, lane = tid & 31;
    int mw = warp & 7, nh = warp >> 3;
    int gid = lane >> 2, tig = lane & 3;
    int row0 = mw * 16 + gid;
    int row1 = row0 + 8;

    for (int t = 0; t < blockLen; t++) {
        // build A fragments: X from fp32 tile (split in regs), H from bf16 tiles
        uint32_t aXh[4][4], aXl[4][4], aHh[4][4], aHl[4][4];
#pragma unroll
        for (int kt = 0; kt < 4; kt++) {
            int kb = kt * 16 + 2 * tig;
            float2 v;
            v = *(float2*)(sX + row0 * PADX + kb);     split2(v, aXh[kt][0], aXl[kt][0]);
            v = *(float2*)(sX + row1 * PADX + kb);     split2(v, aXh[kt][1], aXl[kt][1]);
            v = *(float2*)(sX + row0 * PADX + kb + 8); split2(v, aXh[kt][2], aXl[kt][2]);
            v = *(float2*)(sX + row1 * PADX + kb + 8); split2(v, aXh[kt][3], aXl[kt][3]);
            const __nv_bfloat16 *r0p, *r1p;
            r0p = sHh + row0 * PADK + kb; r1p = sHh + row1 * PADK + kb;
            aHh[kt][0] = *(const uint32_t*)(r0p);
            aHh[kt][1] = *(const uint32_t*)(r1p);
            aHh[kt][2] = *(const uint32_t*)(r0p + 8);
            aHh[kt][3] = *(const uint32_t*)(r1p + 8);
            r0p = sHl + row0 * PADK + kb; r1p = sHl + row1 * PADK + kb;
            aHl[kt][0] = *(const uint32_t*)(r0p);
            aHl[kt][1] = *(const uint32_t*)(r1p);
            aHl[kt][2] = *(const uint32_t*)(r0p + 8);
            aHl[kt][3] = *(const uint32_t*)(r1p + 8);
        }
        __syncthreads();   // frag reads done: X tile free for prefetch, H tiles free for epilogue

        if (t + 1 < blockLen) gather_async(sX, sIdx, t + 1, tid);
        asm volatile("cp.async.commit_group;" ::: "memory");

        for (int c = nh * 4; c < nh * 4 + 4; c++) {
            float ci[3][4], ch[3][4];
#pragma unroll
            for (int j = 0; j < 3; j++) {
                int nb = c * 24 + j * 8 + 2 * tig;
                float b0 = sBih[nb], b1 = sBih[nb + 1];
                ci[j][0] = b0; ci[j][1] = b1; ci[j][2] = b0; ci[j][3] = b1;
                float d0 = sBhh[nb], d1 = sBhh[nb + 1];
                ch[j][0] = d0; ch[j][1] = d1; ch[j][2] = d0; ch[j][3] = d1;
            }
#pragma unroll
            for (int kt = 0; kt < 4; kt++) {
#pragma unroll
                for (int j = 0; j < 3; j++) {
                    int o = (c * 24 + j * 8 + gid) * WST + kt * 4 + tig;
                    uint2 wA = sW[0 * 192 * WST + o];
                    uint2 wB = sW[1 * 192 * WST + o];
                    uint2 wC = sW[2 * 192 * WST + o];
                    uint2 wD = sW[3 * 192 * WST + o];
                    mma16816(ci[j], aXh[kt], wA.x, wA.y);
                    mma16816(ci[j], aXl[kt], wA.x, wA.y);
                    mma16816(ci[j], aXh[kt], wB.x, wB.y);
                    mma16816(ch[j], aHh[kt], wC.x, wC.y);
                    mma16816(ch[j], aHl[kt], wC.x, wC.y);
                    mma16816(ch[j], aHh[kt], wD.x, wD.y);
                }
            }
#pragma unroll
            for (int half = 0; half < 2; half++) {
                int lrow = (half == 0) ? row0 : row1;
                int p = sOrd[lrow];
                int valid = sIdx[lrow * TMAX + t] >= 0;
                int ri = half * 2;
                int ubase = c * 8 + 2 * tig;
                uint32_t hhp = *(uint32_t*)(sHh + lrow * PADK + ubase);
                uint32_t hlp = *(uint32_t*)(sHl + lrow * PADK + ubase);
                __nv_bfloat162 hh2 = *(__nv_bfloat162*)&hhp;
                __nv_bfloat162 hl2 = *(__nv_bfloat162*)&hlp;
                float hold0 = __bfloat162float(hh2.x) + __bfloat162float(hl2.x);
                float hold1 = __bfloat162float(hh2.y) + __bfloat162float(hl2.y);
                float r0 = fsigm(ci[0][ri] + ch[0][ri]);
                float z0 = fsigm(ci[1][ri] + ch[1][ri]);
                float n0 = ftanh(ci[2][ri] + r0 * ch[2][ri]);
                float hn0 = valid ? ((1.f - z0) * n0 + z0 * hold0) : hold0;
                float r1 = fsigm(ci[0][ri + 1] + ch[0][ri + 1]);
                float z1 = fsigm(ci[1][ri + 1] + ch[1][ri + 1]);
                float n1 = ftanh(ci[2][ri + 1] + r1 * ch[2][ri + 1]);
                float hn1 = valid ? ((1.f - z1) * n1 + z1 * hold1) : hold1;
                float h0f = __bfloat162float(__float2bfloat16(hn0));
                float h1f = __bfloat162float(__float2bfloat16(hn1));
                *(uint32_t*)(sHh + lrow * PADK + ubase) = packbf(hn0, hn1);
                *(uint32_t*)(sHl + lrow * PADK + ubase) = packbf(hn0 - h0f, hn1 - h1f);
                if (p >= 0) {
                    float2 o2 = make_float2(valid ? hn0 : 0.f, valid ? hn1 : 0.f);
                    __stcs((float2*)(g_pss + p * 576 + (t + 1) * 64 + ubase), o2);
                }
            }
        }
        asm volatile("cp.async.wait_group 0;" ::: "memory");
        __syncthreads();   // epilogue h-writes + prefetched X visible
    }

    for (int i = tid; i < 128 * 64; i += 512) {
        int pl = i >> 6, k = i & 63;
        int p = sOrd[pl];
        if (p >= 0)
            g_path_state[p * 64 + k] =
                __bfloat162float(sHh[pl * PADK + k]) + __bfloat162float(sHl[pl * PADK + k]);
    }
}

// ---------------------------------------------------------------------------
// Link GRU via MMA: one step, dense. x = g_pa, h = g_link_state (in/out).
// ---------------------------------------------------------------------------
__global__ void __launch_bounds__(512, 1) gru_link_mma() {
    extern __shared__ __align__(16) char smraw[];
    uint2* sW   = (uint2*)smraw;                      // [4][192][WST]
    float* sX   = (float*)(sW + 4 * 192 * WST);       // [128][PADX]
    float* sH   = sX + 128 * PADX;                    // [128][PADX]
    float* sBih = sH + 128 * PADX;                    // [192]
    float* sBhh = sBih + 192;

    int tid = threadIdx.x;
    int lbase = blockIdx.x * 128;

    for (int i = tid; i < 4 * 192 * WST; i += 512) sW[i] = g_wpc[i];
    if (tid < 192) { sBih[tid] = g_bihc_p[tid]; sBhh[tid] = g_bhhc_p[tid]; }
    for (int i = tid; i < 128 * 64; i += 512) {
        int pl = i >> 6, k = i & 63;
        int l = lbase + pl;
        sX[pl * PADX + k] = (l < NLINK) ? g_pa[l * 64 + k] : 0.f;
        sH[pl * PADX + k] = (l < NLINK) ? g_link_state[l * 64 + k] : 0.f;
    }
    __syncthreads();

    int warp = tid >> 5, lane = tid & 31;
    int mw = warp & 7, nh = warp >> 3;
    int gid = lane >> 2, tig = lane & 3;
    int row0 = mw * 16 + gid;
    int row1 = row0 + 8;

    uint32_t aXh[4][4], aXl[4][4], aHh[4][4], aHl[4][4];
#pragma unroll
    for (int kt = 0; kt < 4; kt++) {
        int kb = kt * 16 + 2 * tig;
        float2 v;
        v = *(float2*)(sX + row0 * PADX + kb);     split2(v, aXh[kt][0], aXl[kt][0]);
        v = *(float2*)(sX + row1 * PADX + kb);     split2(v, aXh[kt][1], aXl[kt][1]);
        v = *(float2*)(sX + row0 * PADX + kb + 8); split2(v, aXh[kt][2], aXl[kt][2]);
        v = *(float2*)(sX + row1 * PADX + kb + 8); split2(v, aXh[kt][3], aXl[kt][3]);
        v = *(float2*)(sH + row0 * PADX + kb);     split2(v, aHh[kt][0], aHl[kt][0]);
        v = *(float2*)(sH + row1 * PADX + kb);     split2(v, aHh[kt][1], aHl[kt][1]);
        v = *(float2*)(sH + row0 * PADX + kb + 8); split2(v, aHh[kt][2], aHl[kt][2]);
        v = *(float2*)(sH + row1 * PADX + kb + 8); split2(v, aHh[kt][3], aHl[kt][3]);
    }

    for (int c = nh * 4; c < nh * 4 + 4; c++) {
        float ci[3][4], ch[3][4];
#pragma unroll
        for (int j = 0; j < 3; j++) {
            int nb = c * 24 + j * 8 + 2 * tig;
            float b0 = sBih[nb], b1 = sBih[nb + 1];
            ci[j][0] = b0; ci[j][1] = b1; ci[j][2] = b0; ci[j][3] = b1;
            float d0 = sBhh[nb], d1 = sBhh[nb + 1];
            ch[j][0] = d0; ch[j][1] = d1; ch[j][2] = d0; ch[j][3] = d1;
        }
#pragma unroll
        for (int kt = 0; kt < 4; kt++) {
#pragma unroll
            for (int j = 0; j < 3; j++) {
                int o = (c * 24 + j * 8 + gid) * WST + kt * 4 + tig;
                uint2 wA = sW[0 * 192 * WST + o];
                uint2 wB = sW[1 * 192 * WST + o];
                uint2 wC = sW[2 * 192 * WST + o];
                uint2 wD = sW[3 * 192 * WST + o];
                mma16816(ci[j], aXh[kt], wA.x, wA.y);
                mma16816(ci[j], aXl[kt], wA.x, wA.y);
                mma16816(ci[j], aXh[kt], wB.x, wB.y);
                mma16816(ch[j], aHh[kt], wC.x, wC.y);
                mma16816(ch[j], aHl[kt], wC.x, wC.y);
                mma16816(ch[j], aHh[kt], wD.x, wD.y);
            }
        }
#pragma unroll
        for (int half = 0; half < 2; half++) {
            int lrow = (half == 0) ? row0 : row1;
            int l = lbase + lrow;
            int ri = half * 2;
            int ubase = c * 8 + 2 * tig;
            float hold0 = sH[lrow * PADX + ubase];
            float hold1 = sH[lrow * PADX + ubase + 1];
            float r0 = fsigm(ci[0][ri] + ch[0][ri]);
            float z0 = fsigm(ci[1][ri] + ch[1][ri]);
            float n0 = ftanh(ci[2][ri] + r0 * ch[2][ri]);
            float hn0 = (1.f - z0) * n0 + z0 * hold0;
            float r1 = fsigm(ci[0][ri + 1] + ch[0][ri + 1]);
            float z1 = fsigm(ci[1][ri + 1] + ch[1][ri + 1]);
            float n1 = ftanh(ci[2][ri + 1] + r1 * ch[2][ri + 1]);
            float hn1 = (1.f - z1) * n1 + z1 * hold1;
            if (l < NLINK)
                *(float2*)(g_link_state + l * 64 + ubase) = make_float2(hn0, hn1);
        }
    }
}

// ---------------------------------------------------------------------------
// Embedding
// ---------------------------------------------------------------------------
template <int TARGET>
__global__ void embed_kernel(const float* __restrict__ x,
                             const float* __restrict__ w1, const float* __restrict__ b1,
                             const float* __restrict__ w2, const float* __restrict__ b2,
                             int n) {
    __shared__ float sWm[64 * 64];
    __shared__ float sw1[64], sb1[64], sb2[64];
    __shared__ float sh1[4][64];
    float* st = (TARGET == 0) ? g_path_state : g_link_state;
    int tid = threadIdx.x;
    for (int i = tid; i < 4096; i += 256) {
        int j = i >> 6, k = i & 63;
        sWm[k * 64 + j] = w2[i];
    }
    if (tid < 64) { sw1[tid] = w1[tid]; sb1[tid] = b1[tid]; sb2[tid] = b2[tid]; }
    __syncthreads();
    int g = tid >> 6, d = tid & 63;
    for (int base = blockIdx.x * 4; base < n; base += gridDim.x * 4) {
        int p = base + g;
        float h1 = 0.0f;
        if (p < n) {
            float t = x[p];
            h1 = fmaxf(t * sw1[d] + sb1[d], 0.0f);
        }
        sh1[g][d] = h1;
        groupbar(g);
        float acc = sb2[d];
#pragma unroll 8
        for (int k = 0; k < 64; k++) acc += sh1[g][k] * sWm[k * 64 + d];
        if (p < n) st[p * 64 + d] = fmaxf(acc, 0.0f);
        groupbar(g);
    }
}

// ---------------------------------------------------------------------------
// Link aggregation (dual accumulator chains for MLP)
// ---------------------------------------------------------------------------
__global__ void agg_kernel(const int* __restrict__ p2l) {
    __shared__ int s_pi[4][NDEG], s_pos[4][NDEG];
    int tid = threadIdx.x;
    int g = tid >> 6, d = tid & 63;
    for (int base = blockIdx.x * 4; base < NLINK; base += gridDim.x * 4) {
        int l = base + g;
        if (l < NLINK && d < NDEG) {
            s_pi[g][d]  = p2l[(l * NDEG + d) * 2];
            s_pos[g][d] = p2l[(l * NDEG + d) * 2 + 1];
        }
        groupbar(g);
        if (l < NLINK) {
            float mn0 = INFINITY, mx0 = -INFINITY, sm0 = 0.0f;
            float mn1 = INFINITY, mx1 = -INFINITY, sm1 = 0.0f;
            int c0 = 0, c1 = 0;
#pragma unroll 4
            for (int e = 0; e < NDEG; e += 2) {
                int pi0 = s_pi[g][e];
                int pi1 = s_pi[g][e + 1];
                if (pi0 >= 0) {
                    float v = g_pss[(pi0 * 9 + s_pos[g][e]) * 64 + d];
                    c0++;
                    mn0 = fminf(mn0, v); mx0 = fmaxf(mx0, v); sm0 += v;
                }
                if (pi1 >= 0) {
                    float v = g_pss[(pi1 * 9 + s_pos[g][e + 1]) * 64 + d];
                    c1++;
                    mn1 = fminf(mn1, v); mx1 = fmaxf(mx1, v); sm1 += v;
                }
            }
            float vmin = fminf(mn0, mn1);
            float vmax = fmaxf(mx0, mx1);
            float vsum = sm0 + sm1;
            int cnt = c0 + c1;
            float mean = vsum / (float)(cnt > 0 ? cnt : 1);
            g_agg[l * 256 + d]        = vmin;
            g_agg[l * 256 + 64 + d]   = vmax;
            g_agg[l * 256 + 128 + d]  = vsum;
            g_agg[l * 256 + 192 + d]  = mean;
        }
        groupbar(g);
    }
}

// ---------------------------------------------------------------------------
// Grouped batched matvec + relu, float4 inner loop.
// SRC/DST: 0=g_agg,1=g_t1,2=g_t2,3=g_pa.
// ---------------------------------------------------------------------------
__device__ __forceinline__ float* buf_sel(int s) {
    if (s == 0) return g_agg;
    if (s == 1) return g_t1;
    if (s == 2) return g_t2;
    return g_pa;
}

template <int IN, int OUT, int NL, int GR, int SRC, int DST>
__global__ void __launch_bounds__(OUT * GR) matvec_relu(const float* __restrict__ W,
                                                        const float* __restrict__ b, int n) {
    extern __shared__ float sm[];
    float* sWT = sm;                 // [IN][OUT] (k-major)
    float* sb  = sWT + IN * OUT;     // OUT
    float* sin = sb + OUT;           // [GR][NL*IN]
    const float* in = buf_sel(SRC);
    float* out = buf_sel(DST);
    int tid = threadIdx.x;
    const int NTH = OUT * GR;
    for (int i = tid; i < IN * OUT; i += NTH) {
        int j = i / IN, k = i % IN;
        sWT[k * OUT + j] = W[i];
    }
    if (tid < OUT) sb[tid] = b[tid];
    __syncthreads();
    int g = tid / OUT, j = tid % OUT;
    float* gin = sin + g * NL * IN;
    for (int l0 = (blockIdx.x * GR + g) * NL; l0 < n; l0 += gridDim.x * GR * NL) {
        // vectorized staging: float4 per thread
        for (int i4 = j; i4 < NL * IN / 4; i4 += OUT) {
            int i = i4 * 4;
            int ll = l0 + i / IN;
            int kk = i % IN;
            float4 v = make_float4(0.f, 0.f, 0.f, 0.f);
            if (ll < n) v = *(const float4*)(in + ll * IN + kk);
            *(float4*)(gin + i) = v;
        }
        asm volatile("bar.sync %0, %1;" :: "r"(g + 1), "r"(OUT) : "memory");
        float acc[NL];
#pragma unroll
        for (int q = 0; q < NL; q++) acc[q] = sb[j];
        for (int k = 0; k < IN; k += 4) {
            float w0 = sWT[k * OUT + j];
            float w1 = sWT[(k + 1) * OUT + j];
            float w2 = sWT[(k + 2) * OUT + j];
            float w3 = sWT[(k + 3) * OUT + j];
#pragma unroll
            for (int q = 0; q < NL; q++) {
                float4 gv = *(const float4*)(gin + q * IN + k);
                acc[q] = fmaf(gv.x, w0, acc[q]);
                acc[q] = fmaf(gv.y, w1, acc[q]);
                acc[q] = fmaf(gv.z, w2, acc[q]);
                acc[q] = fmaf(gv.w, w3, acc[q]);
            }
        }
#pragma unroll
        for (int q = 0; q < NL; q++) {
            int ll = l0 + q;
            if (ll < n) out[ll * OUT + j] = fmaxf(acc[q], 0.0f);
        }
        asm volatile("bar.sync %0, %1;" :: "r"(g + 1), "r"(OUT) : "memory");
    }
}

__global__ void copy_out_kernel(float* __restrict__ out, int out_size) {
    const int n1 = NPATH * DS;
    const int n2 = n1 + NLINK * DS;
    for (int i = blockIdx.x * blockDim.x + threadIdx.x; i < out_size;
         i += gridDim.x * blockDim.x) {
        float v = 0.0f;
        if (i < n1) v = g_path_state[i];
        else if (i < n2) v = g_link_state[i - n1];
        out[i] = v;
    }
}

extern "C" void kernel_launch(void* const* d_in, const int* in_sizes, int n_in,
                              void* d_out, int out_size) {
    const float* traffic   = (const float*)d_in[0];
    const float* capacity  = (const float*)d_in[1];
    const int*   l2p       = (const int*)d_in[2];
    const int*   p2l       = (const int*)d_in[3];
    const float* pe_w1 = (const float*)d_in[4];
    const float* pe_b1 = (const float*)d_in[5];
    const float* pe_w2 = (const float*)d_in[6];
    const float* pe_b2 = (const float*)d_in[7];
    const float* le_w1 = (const float*)d_in[8];
    const float* le_b1 = (const float*)d_in[9];
    const float* le_w2 = (const float*)d_in[10];
    const float* le_b2 = (const float*)d_in[11];
    const float* gru_wih = (const float*)d_in[12];
    const float* gru_whh = (const float*)d_in[13];
    const float* gru_bih = (const float*)d_in[14];
    const float* gru_bhh = (const float*)d_in[15];
    const float* cell_wih = (const float*)d_in[16];
    const float* cell_whh = (const float*)d_in[17];
    const float* cell_bih = (const float*)d_in[18];
    const float* cell_bhh = (const float*)d_in[19];
    const float* am_w1 = (const float*)d_in[20];
    const float* am_b1 = (const float*)d_in[21];
    const float* am_w2 = (const float*)d_in[22];
    const float* am_b2 = (const float*)d_in[23];
    const float* am_w3 = (const float*)d_in[24];
    const float* am_b3 = (const float*)d_in[25];

    const size_t smem_mma  = (size_t)(4 * 192 * WST) * 8 + (size_t)(128 * PADX) * 4
                           + (size_t)(2 * 128 * PADK) * 2 + (size_t)(2 * 192) * 4
                           + (size_t)(128 * TMAX + 128 + 128 + 4) * 4;
    const size_t smem_link = (size_t)(4 * 192 * WST) * 8 + (size_t)(2 * 128 * PADX) * 4
                           + (size_t)(2 * 192) * 4;
    const size_t smem_l1 = (size_t)(256 * 128 + 128 + 4 * 16 * 256) * 4;
    const size_t smem_l2 = (size_t)(128 * 128 + 128 + 4 * 16 * 128) * 4;
    const size_t smem_l3 = (size_t)(128 * 64 + 64 + 8 * 16 * 128) * 4;

    cudaFuncSetAttribute(gru_path_mma, cudaFuncAttributeMaxDynamicSharedMemorySize, (int)smem_mma);
    cudaFuncSetAttribute(gru_link_mma, cudaFuncAttributeMaxDynamicSharedMemorySize, (int)smem_link);
    cudaFuncSetAttribute(matvec_relu<256, 128, 16, 4, 0, 1>, cudaFuncAttributeMaxDynamicSharedMemorySize, (int)smem_l1);
    cudaFuncSetAttribute(matvec_relu<128, 128, 16, 4, 1, 2>, cudaFuncAttributeMaxDynamicSharedMemorySize, (int)smem_l2);
    cudaFuncSetAttribute(matvec_relu<128, 64, 16, 8, 2, 3>,  cudaFuncAttributeMaxDynamicSharedMemorySize, (int)smem_l3);

    prep_weights<<<28, 256>>>(gru_wih, gru_whh, gru_bih, gru_bhh,
                              cell_wih, cell_whh, cell_bih, cell_bhh);
    // length sort (once per call; l2p is constant across iterations)
    zero_hist_kernel<<<1, 32>>>();
    len_hist_kernel<<<391, 256>>>(l2p);
    bucket_offsets_kernel<<<1, 32>>>();
    scatter_order_kernel<<<391, 256>>>();

    embed_kernel<0><<<1024, 256>>>(traffic, pe_w1, pe_b1, pe_w2, pe_b2, NPATH);
    embed_kernel<1><<<512, 256>>>(capacity, le_w1, le_b1, le_w2, le_b2, NLINK);

    const int gru_blocks  = (NPATH + 127) / 128;   // 782
    const int link_blocks = (NLINK + 127) / 128;   // 157

    for (int it = 0; it < NITERS; it++) {
        gru_path_mma<<<gru_blocks, 512, smem_mma>>>(l2p);
        agg_kernel<<<2500, 256>>>(p2l);
        matvec_relu<256, 128, 16, 4, 0, 1><<<313, 512, smem_l1>>>(am_w1, am_b1, NLINK);
        matvec_relu<128, 128, 16, 4, 1, 2><<<313, 512, smem_l2>>>(am_w2, am_b2, NLINK);
        matvec_relu<128, 64, 16, 8, 2, 3><<<157, 512, smem_l3>>>(am_w3, am_b3, NLINK);
        gru_link_mma<<<link_blocks, 512, smem_link>>>();
    }

    copy_out_kernel<<<4096, 256>>>((float*)d_out, out_size);
}

// round 17
// speedup vs baseline: 1.3001x; 1.0456x over previous
#include <cuda_runtime.h>
#include <cuda_bf16.h>
#include <math.h>
#include <stdint.h>

#define NPATH 100000
#define NLINK 20000
#define TMAX 8
#define NDEG 48
#define DS 64
#define NITERS 4
#define PADK 72   // bf16 H-tile row stride
#define PADX 68   // fp32 X/H-tile row stride (16B-aligned rows)
#define WST 20    // packed-weight row stride in uint2

// Persistent scratch: uninitialized __device__ globals.
__device__ float g_path_state[NPATH * DS];
__device__ float g_link_state[NLINK * DS];
__device__ float g_pss[NPATH * (TMAX + 1) * DS];
__device__ float g_t2[NLINK * 128];
// Packed GRU weights (path + cell): gate-permuted, bf16 hi/lo, frag-ready uint2.
__device__ uint2 g_wp[4 * 192 * WST];    // path GRU
__device__ uint2 g_wpc[4 * 192 * WST];   // link (cell) GRU
__device__ float g_bih_p[192], g_bhh_p[192];
__device__ float g_bihc_p[192], g_bhhc_p[192];
// Length-sorted path order (counting sort by path length).
__device__ int g_len[NPATH];
__device__ int g_order[NPATH];
__device__ int g_hist[16];
__device__ int g_boff[16];

__device__ __forceinline__ void groupbar(int g) {
    asm volatile("bar.sync %0, 64;" :: "r"(g + 1) : "memory");
}
__device__ __forceinline__ float fsigm(float x) {
    return __fdividef(1.0f, 1.0f + __expf(-x));
}
__device__ __forceinline__ float ftanh(float x) {
    x = fminf(fmaxf(x, -15.0f), 15.0f);
    float e = __expf(-2.0f * x);
    return __fdividef(1.0f - e, 1.0f + e);
}

__device__ __forceinline__ uint32_t packbf(float f0, float f1) {
    __nv_bfloat162 v = __floats2bfloat162_rn(f0, f1);
    return *reinterpret_cast<uint32_t*>(&v);
}
__device__ __forceinline__ void split2(float2 v, uint32_t& hi, uint32_t& lo) {
    __nv_bfloat162 h = __floats2bfloat162_rn(v.x, v.y);
    hi = *reinterpret_cast<uint32_t*>(&h);
    lo = packbf(v.x - __bfloat162float(h.x), v.y - __bfloat162float(h.y));
}

__device__ __forceinline__ void mma16816(float* c, const uint32_t* a, uint32_t b0, uint32_t b1) {
    asm("mma.sync.aligned.m16n8k16.row.col.f32.bf16.bf16.f32 "
        "{%0,%1,%2,%3}, {%4,%5,%6,%7}, {%8,%9}, {%0,%1,%2,%3};"
        : "+f"(c[0]), "+f"(c[1]), "+f"(c[2]), "+f"(c[3])
        : "r"(a[0]), "r"(a[1]), "r"(a[2]), "r"(a[3]), "r"(b0), "r"(b1));
}

// ---------------------------------------------------------------------------
// Length sort (order-invariant output; within-bucket order arbitrary).
// ---------------------------------------------------------------------------
__global__ void zero_hist_kernel() {
    if (threadIdx.x < 16) { g_hist[threadIdx.x] = 0; g_boff[threadIdx.x] = 0; }
}
__global__ void len_hist_kernel(const int* __restrict__ l2p) {
    int p = blockIdx.x * blockDim.x + threadIdx.x;
    if (p < NPATH) {
        int len = 0;
#pragma unroll
        for (int t = 0; t < TMAX; t++) len += (l2p[p * TMAX + t] != -1) ? 1 : 0;
        g_len[p] = len;
        atomicAdd(&g_hist[len], 1);
    }
}
__global__ void bucket_offsets_kernel() {
    if (threadIdx.x == 0) {
        int acc = 0;
        for (int i = 0; i <= TMAX; i++) { g_boff[i] = acc; acc += g_hist[i]; }
    }
}
__global__ void scatter_order_kernel() {
    int p = blockIdx.x * blockDim.x + threadIdx.x;
    if (p < NPATH) {
        int pos = atomicAdd(&g_boff[g_len[p]], 1);
        g_order[pos] = p;
    }
}
// One-time: pss tail zeros (lengths invariant across iterations).
__global__ void pss_tail_zero() {
    for (int i = blockIdx.x * blockDim.x + threadIdx.x; i < NPATH * 64;
         i += gridDim.x * blockDim.x) {
        int p = i >> 6, k = i & 63;
        int L = g_len[p];
        for (int tt = L; tt < TMAX; tt++)
            g_pss[p * 576 + (tt + 1) * 64 + k] = 0.f;
    }
}

// ---------------------------------------------------------------------------
// Weight prep (path + cell): gate-permute, bf16 hi/lo split, frag-pack.
// ---------------------------------------------------------------------------
__device__ __forceinline__ void pack_w(const float* __restrict__ wih,
                                       const float* __restrict__ whh,
                                       uint2* dst, int i) {
    int r = i >> 4, rem2 = i & 15;
    int kt = rem2 >> 2, tig = rem2 & 3;
    int c = r / 24, rr = r % 24, gate = rr >> 3, u = rr & 7;
    int ro = gate * 64 + c * 8 + u;
    int k0 = kt * 16 + 2 * tig;
    const float* wi = wih + ro * 64;
    const float* wh = whh + ro * 64;
    float fi[4] = { wi[k0], wi[k0 + 1], wi[k0 + 8], wi[k0 + 9] };
    float fh[4] = { wh[k0], wh[k0 + 1], wh[k0 + 8], wh[k0 + 9] };
    float hi_i[4], hi_h[4];
#pragma unroll
    for (int q = 0; q < 4; q++) {
        hi_i[q] = __bfloat162float(__float2bfloat16(fi[q]));
        hi_h[q] = __bfloat162float(__float2bfloat16(fh[q]));
    }
    int o = r * WST + kt * 4 + tig;
    uint2 v;
    v.x = packbf(fi[0], fi[1]);                     v.y = packbf(fi[2], fi[3]);
    dst[0 * 192 * WST + o] = v;
    v.x = packbf(fi[0] - hi_i[0], fi[1] - hi_i[1]); v.y = packbf(fi[2] - hi_i[2], fi[3] - hi_i[3]);
    dst[1 * 192 * WST + o] = v;
    v.x = packbf(fh[0], fh[1]);                     v.y = packbf(fh[2], fh[3]);
    dst[2 * 192 * WST + o] = v;
    v.x = packbf(fh[0] - hi_h[0], fh[1] - hi_h[1]); v.y = packbf(fh[2] - hi_h[2], fh[3] - hi_h[3]);
    dst[3 * 192 * WST + o] = v;
}

__global__ void prep_weights(const float* __restrict__ wih, const float* __restrict__ whh,
                             const float* __restrict__ bih, const float* __restrict__ bhh,
                             const float* __restrict__ cwih, const float* __restrict__ cwhh,
                             const float* __restrict__ cbih, const float* __restrict__ cbhh) {
    int i = blockIdx.x * blockDim.x + threadIdx.x;
    if (i < 192) {
        int c = i / 24, rem = i % 24, gate = rem >> 3, u = rem & 7;
        int ro = gate * 64 + c * 8 + u;
        g_bih_p[i] = bih[ro];   g_bhh_p[i] = bhh[ro];
        g_bihc_p[i] = cbih[ro]; g_bhhc_p[i] = cbhh[ro];
    }
    if (i < 3072) pack_w(wih, whh, g_wp, i);
    else if (i >= 4096 && i < 7168) pack_w(cwih, cwhh, g_wpc, i - 4096);
}

// ---------------------------------------------------------------------------
// cp.async gather of one timestep's x rows into fp32 X tile (zero-fill invalid)
// ---------------------------------------------------------------------------
__device__ __forceinline__ void gather_async(float* sX, const int* sIdx, int t, int tid) {
    for (int i = tid; i < 128 * 16; i += 512) {
        int pl = i >> 4, q = i & 15;
        int idx = sIdx[pl * TMAX + t];
        const float* src = g_link_state + (idx >= 0 ? idx : 0) * 64 + q * 4;
        uint32_t dst = (uint32_t)__cvta_generic_to_shared(sX + pl * PADX + q * 4);
        int sz = (idx >= 0) ? 16 : 0;
        asm volatile("cp.async.ca.shared.global [%0], [%1], 16, %2;"
                     :: "r"(dst), "l"(src), "r"(sz) : "memory");
    }
}

// ---------------------------------------------------------------------------
// FUSED path GRU over LENGTH-SORTED paths (tail zeros pre-written once).
// ---------------------------------------------------------------------------
__global__ void __launch_bounds__(512, 1) gru_path_mma(const int* __restrict__ l2p) {
    extern __shared__ __align__(16) char smraw[];
    uint2* sW          = (uint2*)smraw;                       // [4][192][WST]
    float* sX          = (float*)(sW + 4 * 192 * WST);        // [128][PADX] fp32
    __nv_bfloat16* sHh = (__nv_bfloat16*)(sX + 128 * PADX);   // [128][PADK]
    __nv_bfloat16* sHl = sHh + 128 * PADK;
    float* sBih        = (float*)(sHl + 128 * PADK);          // [192]
    float* sBhh        = sBih + 192;
    int*   sIdx        = (int*)(sBhh + 192);                  // [128][TMAX]
    int*   sOrd        = sIdx + 128 * TMAX;                   // [128]
    int*   sBmax       = sOrd + 128;                          // [1]

    int tid = threadIdx.x;
    int pbase = blockIdx.x * 128;

    if (tid < 128) {
        int gp = pbase + tid;
        sOrd[tid] = (gp < NPATH) ? g_order[gp] : -1;
    }
    if (tid == 0) *sBmax = 0;
    __syncthreads();

    for (int i = tid; i < 128 * TMAX; i += 512) {
        int pl = i / TMAX, tt = i % TMAX;
        int p = sOrd[pl];
        sIdx[pl * TMAX + tt] = (p >= 0) ? l2p[p * TMAX + tt] : -1;
    }
    if (tid < 128) {
        int p = sOrd[tid];
        int L = (p >= 0) ? g_len[p] : 0;
        atomicMax(sBmax, L);
    }
    __syncthreads();

    gather_async(sX, sIdx, 0, tid);
    asm volatile("cp.async.commit_group;" ::: "memory");

    for (int i = tid; i < 4 * 192 * WST; i += 512) sW[i] = g_wp[i];
    if (tid < 192) { sBih[tid] = g_bih_p[tid]; sBhh[tid] = g_bhh_p[tid]; }

    for (int i = tid; i < 128 * 64; i += 512) {
        int pl = i >> 6, k = i & 63;
        int p = sOrd[pl];
        float hv = 0.f;
        if (p >= 0) {
            hv = g_path_state[p * 64 + k];
            __stcs(&g_pss[p * 576 + k], hv);
        }
        __nv_bfloat16 hh = __float2bfloat16(hv);
        sHh[pl * PADK + k] = hh;
        sHl[pl * PADK + k] = __float2bfloat16(hv - __bfloat162float(hh));
    }
    asm volatile("cp.async.wait_group 0;" ::: "memory");
    __syncthreads();

    int blockLen = *sBmax;
    int warp = tid >> 5, lane = tid & 31;
    int mw = warp & 7, nh = warp >> 3;
    int gid = lane >> 2, tig = lane & 3;
    int row0 = mw * 16 + gid;
    int row1 = row0 + 8;

    for (int t = 0; t < blockLen; t++) {
        uint32_t aXh[4][4], aXl[4][4], aHh[4][4], aHl[4][4];
#pragma unroll
        for (int kt = 0; kt < 4; kt++) {
            int kb = kt * 16 + 2 * tig;
            float2 v;
            v = *(float2*)(sX + row0 * PADX + kb);     split2(v, aXh[kt][0], aXl[kt][0]);
            v = *(float2*)(sX + row1 * PADX + kb);     split2(v, aXh[kt][1], aXl[kt][1]);
            v = *(float2*)(sX + row0 * PADX + kb + 8); split2(v, aXh[kt][2], aXl[kt][2]);
            v = *(float2*)(sX + row1 * PADX + kb + 8); split2(v, aXh[kt][3], aXl[kt][3]);
            const __nv_bfloat16 *r0p, *r1p;
            r0p = sHh + row0 * PADK + kb; r1p = sHh + row1 * PADK + kb;
            aHh[kt][0] = *(const uint32_t*)(r0p);
            aHh[kt][1] = *(const uint32_t*)(r1p);
            aHh[kt][2] = *(const uint32_t*)(r0p + 8);
            aHh[kt][3] = *(const uint32_t*)(r1p + 8);
            r0p = sHl + row0 * PADK + kb; r1p = sHl + row1 * PADK + kb;
            aHl[kt][0] = *(const uint32_t*)(r0p);
            aHl[kt][1] = *(const uint32_t*)(r1p);
            aHl[kt][2] = *(const uint32_t*)(r0p + 8);
            aHl[kt][3] = *(const uint32_t*)(r1p + 8);
        }
        __syncthreads();

        if (t + 1 < blockLen) gather_async(sX, sIdx, t + 1, tid);
        asm volatile("cp.async.commit_group;" ::: "memory");

        for (int c = nh * 4; c < nh * 4 + 4; c++) {
            float ci[3][4], ch[3][4];
#pragma unroll
            for (int j = 0; j < 3; j++) {
                int nb = c * 24 + j * 8 + 2 * tig;
                float b0 = sBih[nb], b1 = sBih[nb + 1];
                ci[j][0] = b0; ci[j][1] = b1; ci[j][2] = b0; ci[j][3] = b1;
                float d0 = sBhh[nb], d1 = sBhh[nb + 1];
                ch[j][0] = d0; ch[j][1] = d1; ch[j][2] = d0; ch[j][3] = d1;
            }
#pragma unroll
            for (int kt = 0; kt < 4; kt++) {
#pragma unroll
                for (int j = 0; j < 3; j++) {
                    int o = (c * 24 + j * 8 + gid) * WST + kt * 4 + tig;
                    uint2 wA = sW[0 * 192 * WST + o];
                    uint2 wB = sW[1 * 192 * WST + o];
                    uint2 wC = sW[2 * 192 * WST + o];
                    uint2 wD = sW[3 * 192 * WST + o];
                    mma16816(ci[j], aXh[kt], wA.x, wA.y);
                    mma16816(ci[j], aXl[kt], wA.x, wA.y);
                    mma16816(ci[j], aXh[kt], wB.x, wB.y);
                    mma16816(ch[j], aHh[kt], wC.x, wC.y);
                    mma16816(ch[j], aHl[kt], wC.x, wC.y);
                    mma16816(ch[j], aHh[kt], wD.x, wD.y);
                }
            }
#pragma unroll
            for (int half = 0; half < 2; half++) {
                int lrow = (half == 0) ? row0 : row1;
                int p = sOrd[lrow];
                int valid = sIdx[lrow * TMAX + t] >= 0;
                int ri = half * 2;
                int ubase = c * 8 + 2 * tig;
                uint32_t hhp = *(uint32_t*)(sHh + lrow * PADK + ubase);
                uint32_t hlp = *(uint32_t*)(sHl + lrow * PADK + ubase);
                __nv_bfloat162 hh2 = *(__nv_bfloat162*)&hhp;
                __nv_bfloat162 hl2 = *(__nv_bfloat162*)&hlp;
                float hold0 = __bfloat162float(hh2.x) + __bfloat162float(hl2.x);
                float hold1 = __bfloat162float(hh2.y) + __bfloat162float(hl2.y);
                float r0 = fsigm(ci[0][ri] + ch[0][ri]);
                float z0 = fsigm(ci[1][ri] + ch[1][ri]);
                float n0 = ftanh(ci[2][ri] + r0 * ch[2][ri]);
                float hn0 = valid ? ((1.f - z0) * n0 + z0 * hold0) : hold0;
                float r1 = fsigm(ci[0][ri + 1] + ch[0][ri + 1]);
                float z1 = fsigm(ci[1][ri + 1] + ch[1][ri + 1]);
                float n1 = ftanh(ci[2][ri + 1] + r1 * ch[2][ri + 1]);
                float hn1 = valid ? ((1.f - z1) * n1 + z1 * hold1) : hold1;
                float h0f = __bfloat162float(__float2bfloat16(hn0));
                float h1f = __bfloat162float(__float2bfloat16(hn1));
                *(uint32_t*)(sHh + lrow * PADK + ubase) = packbf(hn0, hn1);
                *(uint32_t*)(sHl + lrow * PADK + ubase) = packbf(hn0 - h0f, hn1 - h1f);
                if (p >= 0 && valid) {
                    __stcs((float2*)(g_pss + p * 576 + (t + 1) * 64 + ubase),
                           make_float2(hn0, hn1));
                }
            }
        }
        asm volatile("cp.async.wait_group 0;" ::: "memory");
        __syncthreads();
    }

    for (int i = tid; i < 128 * 64; i += 512) {
        int pl = i >> 6, k = i & 63;
        int p = sOrd[pl];
        if (p >= 0)
            g_path_state[p * 64 + k] =
                __bfloat162float(sHh[pl * PADK + k]) + __bfloat162float(sHl[pl * PADK + k]);
    }
}

// ---------------------------------------------------------------------------
// FUSED agg + MLP layer1 + layer2. Block stages w1+w2 once; per pass of 16
// links: gather pss -> agg (smem) -> layer1 (smem) -> layer2 -> g_t2.
// ---------------------------------------------------------------------------
__global__ void __launch_bounds__(512, 1) agg_mlp12(const int* __restrict__ p2l,
                                                    const float* __restrict__ w1,
                                                    const float* __restrict__ b1,
                                                    const float* __restrict__ w2,
                                                    const float* __restrict__ b2) {
    extern __shared__ __align__(16) float sm[];
    float* sW1  = sm;                    // [256][128] k-major: sW1[k*128+j]
    float* sW2  = sW1 + 32768;           // [128][128] k-major
    float* sB1  = sW2 + 16384;           // 128
    float* sB2  = sB1 + 128;             // 128
    float* sAgg = sB2 + 128;             // [16][256]
    float* sT1  = sAgg + 4096;           // [16][128]
    int*   sPi  = (int*)(sT1 + 2048);    // [16*48]
    int*   sPos = sPi + 768;             // [16*48]

    int tid = threadIdx.x;
    for (int i = tid; i < 256 * 128; i += 512) {
        int j = i / 256, k = i % 256;
        sW1[k * 128 + j] = w1[i];
    }
    for (int i = tid; i < 128 * 128; i += 512) {
        int j = i / 128, k = i % 128;
        sW2[k * 128 + j] = w2[i];
    }
    if (tid < 128) { sB1[tid] = b1[tid]; sB2[tid] = b2[tid]; }
    __syncthreads();

    int j = tid & 127, grp = tid >> 7;   // 4 groups of 128 threads

    for (int l0 = blockIdx.x * 16; l0 < NLINK; l0 += gridDim.x * 16) {
        for (int i = tid; i < 16 * 48; i += 512) {
            int li = i / 48, e = i % 48;
            int l = l0 + li;
            sPi[i]  = (l < NLINK) ? p2l[(l * NDEG + e) * 2]     : -1;
            sPos[i] = (l < NLINK) ? p2l[(l * NDEG + e) * 2 + 1] : 0;
        }
        __syncthreads();
        for (int it = tid; it < 16 * 64; it += 512) {
            int li = it >> 6, d = it & 63;
            float mn0 = INFINITY, mx0 = -INFINITY, sm0 = 0.0f;
            float mn1 = INFINITY, mx1 = -INFINITY, sm1 = 0.0f;
            int c0 = 0, c1 = 0;
            if (l0 + li < NLINK) {
#pragma unroll 4
                for (int e = 0; e < NDEG; e += 2) {
                    int pi0 = sPi[li * 48 + e];
                    int pi1 = sPi[li * 48 + e + 1];
                    if (pi0 >= 0) {
                        float v = g_pss[(pi0 * 9 + sPos[li * 48 + e]) * 64 + d];
                        c0++; mn0 = fminf(mn0, v); mx0 = fmaxf(mx0, v); sm0 += v;
                    }
                    if (pi1 >= 0) {
                        float v = g_pss[(pi1 * 9 + sPos[li * 48 + e + 1]) * 64 + d];
                        c1++; mn1 = fminf(mn1, v); mx1 = fmaxf(mx1, v); sm1 += v;
                    }
                }
            }
            float vmin = fminf(mn0, mn1), vmax = fmaxf(mx0, mx1);
            float vsum = sm0 + sm1;
            int cnt = c0 + c1;
            if (cnt == 0) { vmin = 0.f; vmax = 0.f; }
            float mean = vsum / (float)(cnt > 0 ? cnt : 1);
            sAgg[li * 256 + d]       = vmin;
            sAgg[li * 256 + 64 + d]  = vmax;
            sAgg[li * 256 + 128 + d] = vsum;
            sAgg[li * 256 + 192 + d] = mean;
        }
        __syncthreads();
        {
            float acc[4];
#pragma unroll
            for (int q = 0; q < 4; q++) acc[q] = sB1[j];
            for (int k = 0; k < 256; k += 4) {
                float w0 = sW1[k * 128 + j];
                float wq1 = sW1[(k + 1) * 128 + j];
                float wq2 = sW1[(k + 2) * 128 + j];
                float wq3 = sW1[(k + 3) * 128 + j];
#pragma unroll
                for (int q = 0; q < 4; q++) {
                    float4 gv = *(const float4*)(sAgg + (grp * 4 + q) * 256 + k);
                    acc[q] = fmaf(gv.x, w0, acc[q]);
                    acc[q] = fmaf(gv.y, wq1, acc[q]);
                    acc[q] = fmaf(gv.z, wq2, acc[q]);
                    acc[q] = fmaf(gv.w, wq3, acc[q]);
                }
            }
#pragma unroll
            for (int q = 0; q < 4; q++)
                sT1[(grp * 4 + q) * 128 + j] = fmaxf(acc[q], 0.0f);
        }
        __syncthreads();
        {
            float acc[4];
#pragma unroll
            for (int q = 0; q < 4; q++) acc[q] = sB2[j];
            for (int k = 0; k < 128; k += 4) {
                float w0 = sW2[k * 128 + j];
                float wq1 = sW2[(k + 1) * 128 + j];
                float wq2 = sW2[(k + 2) * 128 + j];
                float wq3 = sW2[(k + 3) * 128 + j];
#pragma unroll
                for (int q = 0; q < 4; q++) {
                    float4 gv = *(const float4*)(sT1 + (grp * 4 + q) * 128 + k);
                    acc[q] = fmaf(gv.x, w0, acc[q]);
                    acc[q] = fmaf(gv.y, wq1, acc[q]);
                    acc[q] = fmaf(gv.z, wq2, acc[q]);
                    acc[q] = fmaf(gv.w, wq3, acc[q]);
                }
            }
#pragma unroll
            for (int q = 0; q < 4; q++) {
                int l = l0 + grp * 4 + q;
                if (l < NLINK) g_t2[l * 128 + j] = fmaxf(acc[q], 0.0f);
            }
        }
        __syncthreads();
    }
}

// ---------------------------------------------------------------------------
// FUSED MLP layer3 + link GRU (MMA). pa stays in smem (sX); cell weights
// staged into a union region after the t2/w3 phase retires.
// ---------------------------------------------------------------------------
__global__ void __launch_bounds__(512, 1) mlp3_link(const float* __restrict__ w3,
                                                    const float* __restrict__ b3) {
    extern __shared__ __align__(16) float sm[];
    float* sX   = sm;                    // [128][PADX] (pa)
    float* sH   = sX + 128 * PADX;       // [128][PADX]
    float* sBih = sH + 128 * PADX;       // 192 (cell)
    float* sBhh = sBih + 192;            // 192
    float* sB3  = sBhh + 192;            // 64
    float* U    = sB3 + 64;              // union region
    float* sT2  = U;                     // [128][128]  (phase 1)
    float* sW3T = sT2 + 128 * 128;       // [128][64] k-major (phase 1)
    uint2* sWc  = (uint2*)U;             // [4][192][WST] (phase 2)

    int tid = threadIdx.x;
    int lbase = blockIdx.x * 128;

    for (int i = tid; i < 128 * 128; i += 512) {
        int pl = i >> 7, k = i & 127;
        int l = lbase + pl;
        sT2[i] = (l < NLINK) ? g_t2[l * 128 + k] : 0.f;
    }
    for (int i = tid; i < 64 * 128; i += 512) {
        int jj = i / 128, k = i % 128;
        sW3T[k * 64 + jj] = w3[i];
    }
    if (tid < 64) sB3[tid] = b3[tid];
    if (tid < 192) { sBih[tid] = g_bihc_p[tid]; sBhh[tid] = g_bhhc_p[tid]; }
    for (int i = tid; i < 128 * 64; i += 512) {
        int pl = i >> 6, k = i & 63;
        int l = lbase + pl;
        sH[pl * PADX + k] = (l < NLINK) ? g_link_state[l * 64 + k] : 0.f;
    }
    __syncthreads();

    {
        int j = tid & 63, grp = tid >> 6;
        float acc[16];
#pragma unroll
        for (int q = 0; q < 16; q++) acc[q] = sB3[j];
        for (int k = 0; k < 128; k += 4) {
            float w0 = sW3T[k * 64 + j];
            float wq1 = sW3T[(k + 1) * 64 + j];
            float wq2 = sW3T[(k + 2) * 64 + j];
            float wq3 = sW3T[(k + 3) * 64 + j];
#pragma unroll
            for (int q = 0; q < 16; q++) {
                float4 gv = *(const float4*)(sT2 + (grp * 16 + q) * 128 + k);
                acc[q] = fmaf(gv.x, w0, acc[q]);
                acc[q] = fmaf(gv.y, wq1, acc[q]);
                acc[q] = fmaf(gv.z, wq2, acc[q]);
                acc[q] = fmaf(gv.w, wq3, acc[q]);
            }
        }
#pragma unroll
        for (int q = 0; q < 16; q++)
            sX[(grp * 16 + q) * PADX + j] = fmaxf(acc[q], 0.0f);
    }
    __syncthreads();

    for (int i = tid; i < 4 * 192 * WST; i += 512) sWc[i] = g_wpc[i];
    __syncthreads();

    int warp = tid >> 5, lane = tid & 31;
    int mw = warp & 7, nh = warp >> 3;
    int gid = lane >> 2, tig = lane & 3;
    int row0 = mw * 16 + gid;
    int row1 = row0 + 8;

    uint32_t aXh[4][4], aXl[4][4], aHh[4][4], aHl[4][4];
#pragma unroll
    for (int kt = 0; kt < 4; kt++) {
        int kb = kt * 16 + 2 * tig;
        float2 v;
        v = *(float2*)(sX + row0 * PADX + kb);     split2(v, aXh[kt][0], aXl[kt][0]);
        v = *(float2*)(sX + row1 * PADX + kb);     split2(v, aXh[kt][1], aXl[kt][1]);
        v = *(float2*)(sX + row0 * PADX + kb + 8); split2(v, aXh[kt][2], aXl[kt][2]);
        v = *(float2*)(sX + row1 * PADX + kb + 8); split2(v, aXh[kt][3], aXl[kt][3]);
        v = *(float2*)(sH + row0 * PADX + kb);     split2(v, aHh[kt][0], aHl[kt][0]);
        v = *(float2*)(sH + row1 * PADX + kb);     split2(v, aHh[kt][1], aHl[kt][1]);
        v = *(float2*)(sH + row0 * PADX + kb + 8); split2(v, aHh[kt][2], aHl[kt][2]);
        v = *(float2*)(sH + row1 * PADX + kb + 8); split2(v, aHh[kt][3], aHl[kt][3]);
    }

    for (int c = nh * 4; c < nh * 4 + 4; c++) {
        float ci[3][4], ch[3][4];
#pragma unroll
        for (int j = 0; j < 3; j++) {
            int nb = c * 24 + j * 8 + 2 * tig;
            float b0 = sBih[nb], b1 = sBih[nb + 1];
            ci[j][0] = b0; ci[j][1] = b1; ci[j][2] = b0; ci[j][3] = b1;
            float d0 = sBhh[nb], d1 = sBhh[nb + 1];
            ch[j][0] = d0; ch[j][1] = d1; ch[j][2] = d0; ch[j][3] = d1;
        }
#pragma unroll
        for (int kt = 0; kt < 4; kt++) {
#pragma unroll
            for (int j = 0; j < 3; j++) {
                int o = (c * 24 + j * 8 + gid) * WST + kt * 4 + tig;
                uint2 wA = sWc[0 * 192 * WST + o];
                uint2 wB = sWc[1 * 192 * WST + o];
                uint2 wC = sWc[2 * 192 * WST + o];
                uint2 wD = sWc[3 * 192 * WST + o];
                mma16816(ci[j], aXh[kt], wA.x, wA.y);
                mma16816(ci[j], aXl[kt], wA.x, wA.y);
                mma16816(ci[j], aXh[kt], wB.x, wB.y);
                mma16816(ch[j], aHh[kt], wC.x, wC.y);
                mma16816(ch[j], aHl[kt], wC.x, wC.y);
                mma16816(ch[j], aHh[kt], wD.x, wD.y);
            }
        }
#pragma unroll
        for (int half = 0; half < 2; half++) {
            int lrow = (half == 0) ? row0 : row1;
            int l = lbase + lrow;
            int ri = half * 2;
            int ubase = c * 8 + 2 * tig;
            float hold0 = sH[lrow * PADX + ubase];
            float hold1 = sH[lrow * PADX + ubase + 1];
            float r0 = fsigm(ci[0][ri] + ch[0][ri]);
            float z0 = fsigm(ci[1][ri] + ch[1][ri]);
            float n0 = ftanh(ci[2][ri] + r0 * ch[2][ri]);
            float hn0 = (1.f - z0) * n0 + z0 * hold0;
            float r1 = fsigm(ci[0][ri + 1] + ch[0][ri + 1]);
            float z1 = fsigm(ci[1][ri + 1] + ch[1][ri + 1]);
            float n1 = ftanh(ci[2][ri + 1] + r1 * ch[2][ri + 1]);
            float hn1 = (1.f - z1) * n1 + z1 * hold1;
            if (l < NLINK)
                *(float2*)(g_link_state + l * 64 + ubase) = make_float2(hn0, hn1);
        }
    }
}

// ---------------------------------------------------------------------------
// Embedding
// ---------------------------------------------------------------------------
template <int TARGET>
__global__ void embed_kernel(const float* __restrict__ x,
                             const float* __restrict__ w1, const float* __restrict__ b1,
                             const float* __restrict__ w2, const float* __restrict__ b2,
                             int n) {
    __shared__ float sWm[64 * 64];
    __shared__ float sw1[64], sb1[64], sb2[64];
    __shared__ float sh1[4][64];
    float* st = (TARGET == 0) ? g_path_state : g_link_state;
    int tid = threadIdx.x;
    for (int i = tid; i < 4096; i += 256) {
        int j = i >> 6, k = i & 63;
        sWm[k * 64 + j] = w2[i];
    }
    if (tid < 64) { sw1[tid] = w1[tid]; sb1[tid] = b1[tid]; sb2[tid] = b2[tid]; }
    __syncthreads();
    int g = tid >> 6, d = tid & 63;
    for (int base = blockIdx.x * 4; base < n; base += gridDim.x * 4) {
        int p = base + g;
        float h1 = 0.0f;
        if (p < n) {
            float t = x[p];
            h1 = fmaxf(t * sw1[d] + sb1[d], 0.0f);
        }
        sh1[g][d] = h1;
        groupbar(g);
        float acc = sb2[d];
#pragma unroll 8
        for (int k = 0; k < 64; k++) acc += sh1[g][k] * sWm[k * 64 + d];
        if (p < n) st[p * 64 + d] = fmaxf(acc, 0.0f);
        groupbar(g);
    }
}

__global__ void copy_out_kernel(float* __restrict__ out, int out_size) {
    const int n1 = NPATH * DS;
    const int n2 = n1 + NLINK * DS;
    for (int i = blockIdx.x * blockDim.x + threadIdx.x; i < out_size;
         i += gridDim.x * blockDim.x) {
        float v = 0.0f;
        if (i < n1) v = g_path_state[i];
        else if (i < n2) v = g_link_state[i - n1];
        out[i] = v;
    }
}

extern "C" void kernel_launch(void* const* d_in, const int* in_sizes, int n_in,
                              void* d_out, int out_size) {
    const float* traffic   = (const float*)d_in[0];
    const float* capacity  = (const float*)d_in[1];
    const int*   l2p       = (const int*)d_in[2];
    const int*   p2l       = (const int*)d_in[3];
    const float* pe_w1 = (const float*)d_in[4];
    const float* pe_b1 = (const float*)d_in[5];
    const float* pe_w2 = (const float*)d_in[6];
    const float* pe_b2 = (const float*)d_in[7];
    const float* le_w1 = (const float*)d_in[8];
    const float* le_b1 = (const float*)d_in[9];
    const float* le_w2 = (const float*)d_in[10];
    const float* le_b2 = (const float*)d_in[11];
    const float* gru_wih = (const float*)d_in[12];
    const float* gru_whh = (const float*)d_in[13];
    const float* gru_bih = (const float*)d_in[14];
    const float* gru_bhh = (const float*)d_in[15];
    const float* cell_wih = (const float*)d_in[16];
    const float* cell_whh = (const float*)d_in[17];
    const float* cell_bih = (const float*)d_in[18];
    const float* cell_bhh = (const float*)d_in[19];
    const float* am_w1 = (const float*)d_in[20];
    const float* am_b1 = (const float*)d_in[21];
    const float* am_w2 = (const float*)d_in[22];
    const float* am_b2 = (const float*)d_in[23];
    const float* am_w3 = (const float*)d_in[24];
    const float* am_b3 = (const float*)d_in[25];

    const size_t smem_mma = (size_t)(4 * 192 * WST) * 8 + (size_t)(128 * PADX) * 4
                          + (size_t)(2 * 128 * PADK) * 2 + (size_t)(2 * 192) * 4
                          + (size_t)(128 * TMAX + 128 + 4) * 4;
    const size_t smem_a   = (size_t)(32768 + 16384 + 128 + 128 + 4096 + 2048) * 4
                          + (size_t)(2 * 768) * 4;                       // 228352
    const size_t smem_b   = (size_t)(2 * 128 * PADX + 2 * 192 + 64) * 4
                          + (size_t)(4 * 192 * WST) * 8;                 // 194304

    cudaFuncSetAttribute(gru_path_mma, cudaFuncAttributeMaxDynamicSharedMemorySize, (int)smem_mma);
    cudaFuncSetAttribute(agg_mlp12, cudaFuncAttributeMaxDynamicSharedMemorySize, (int)smem_a);
    cudaFuncSetAttribute(mlp3_link, cudaFuncAttributeMaxDynamicSharedMemorySize, (int)smem_b);

    prep_weights<<<28, 256>>>(gru_wih, gru_whh, gru_bih, gru_bhh,
                              cell_wih, cell_whh, cell_bih, cell_bhh);
    zero_hist_kernel<<<1, 32>>>();
    len_hist_kernel<<<391, 256>>>(l2p);
    bucket_offsets_kernel<<<1, 32>>>();
    scatter_order_kernel<<<391, 256>>>();
    pss_tail_zero<<<2048, 256>>>();

    embed_kernel<0><<<1024, 256>>>(traffic, pe_w1, pe_b1, pe_w2, pe_b2, NPATH);
    embed_kernel<1><<<512, 256>>>(capacity, le_w1, le_b1, le_w2, le_b2, NLINK);

    const int gru_blocks  = (NPATH + 127) / 128;   // 782
    const int link_blocks = (NLINK + 127) / 128;   // 157

    for (int it = 0; it < NITERS; it++) {
        gru_path_mma<<<gru_blocks, 512, smem_mma>>>(l2p);
        agg_mlp12<<<148, 512, smem_a>>>(p2l, am_w1, am_b1, am_w2, am_b2);
        mlp3_link<<<link_blocks, 512, smem_b>>>(am_w3, am_b3);
    }

    copy_out_kernel<<<4096, 256>>>((float*)d_out, out_size);
}